// round 14
// baseline (speedup 1.0000x reference)
#include <cuda_runtime.h>
#include <cuda_fp16.h>
#include <stdint.h>
#include <math.h>

// ---------------- problem constants ----------------
#define S_   256
#define B_   64
#define W_   16
#define Ec_  64
#define Hc_  128
#define E_   300
#define Hw_  512
#define T_   32
#define D_   557
#define Kp_  576
#define NC_  (B_ * S_)
#define VC_  128

// ---------------- scratch: fp16 hi/lo planes for all MMA operands ----------------
__device__ __align__(16) __half g_ch_h[2][2][NC_ * Hc_];
__device__ __align__(16) __half g_ch_l[2][2][NC_ * Hc_];
__device__ float g_char_c[2][NC_ * Hc_];
__device__ float g_cproj[2][VC_ * 4 * Hc_];
__device__ __align__(16) __half g_cwhh_h[2][4 * Hc_ * Hc_];
__device__ __align__(16) __half g_cwhh_l[2][4 * Hc_ * Hc_];
__device__ __align__(16) __half g_x_h[(size_t)NC_ * Kp_];
__device__ __align__(16) __half g_x_l[(size_t)NC_ * Kp_];
__device__ __align__(16) __half g_wih_h[2][4 * Hw_ * Kp_];
__device__ __align__(16) __half g_wih_l[2][4 * Hw_ * Kp_];
__device__ float g_wxproj[2][(size_t)NC_ * 4 * Hw_];
__device__ __align__(16) __half g_wh_h[2][2][B_ * Hw_];
__device__ __align__(16) __half g_wh_l[2][2][B_ * Hw_];
__device__ float g_word_c[2][B_ * Hw_];
__device__ __align__(16) __half g_enc_h[(size_t)NC_ * 2 * Hw_];
__device__ __align__(16) __half g_enc_l[(size_t)NC_ * 2 * Hw_];
__device__ __align__(16) __half g_h1_h[(size_t)NC_ * Hw_];
__device__ __align__(16) __half g_h1_l[(size_t)NC_ * Hw_];
__device__ __align__(16) __half g_ff1w_h[Hw_ * 2 * Hw_];
__device__ __align__(16) __half g_ff1w_l[Hw_ * 2 * Hw_];
__device__ __align__(16) __half g_ff2w_h[T_ * Hw_];
__device__ __align__(16) __half g_ff2w_l[T_ * Hw_];
__device__ float g_logits[NC_ * T_];
__device__ float g_logZ[B_];
__device__ volatile int g_bar_count[2];
__device__ volatile int g_bar_gen[2];

__device__ __forceinline__ float sigf(float x) { return 1.0f / (1.0f + expf(-x)); }

__device__ __forceinline__ void split2h(float v, __half& h, __half& l) {
    __half hh = __float2half_rn(v);
    h = hh;
    l = __float2half_rn(v - __half2float(hh));
}

// fp16 m16n8k16 mma, fp32 accumulate
__device__ __forceinline__ void mma16(float* c, const unsigned* a, const unsigned* b) {
    asm volatile(
        "mma.sync.aligned.m16n8k16.row.col.f32.f16.f16.f32 "
        "{%0,%1,%2,%3}, {%4,%5,%6,%7}, {%8,%9}, {%0,%1,%2,%3};"
        : "+f"(c[0]), "+f"(c[1]), "+f"(c[2]), "+f"(c[3])
        : "r"(a[0]), "r"(a[1]), "r"(a[2]), "r"(a[3]), "r"(b[0]), "r"(b[1]));
}
__device__ __forceinline__ void mma3h(float* c, const unsigned* ah, const unsigned* al,
                                      const unsigned* bh, const unsigned* bl) {
    mma16(c, al, bh);
    mma16(c, ah, bl);
    mma16(c, ah, bh);
}

// warp-collective ldmatrix
__device__ __forceinline__ void ldm_x4(unsigned* r, uint32_t saddr) {
    asm volatile("ldmatrix.sync.aligned.m8n8.x4.shared.b16 {%0,%1,%2,%3}, [%4];"
        : "=r"(r[0]), "=r"(r[1]), "=r"(r[2]), "=r"(r[3]) : "r"(saddr));
}
__device__ __forceinline__ void ldm_x2(unsigned* r, uint32_t saddr) {
    asm volatile("ldmatrix.sync.aligned.m8n8.x2.shared.b16 {%0,%1}, [%2];"
        : "=r"(r[0]), "=r"(r[1]) : "r"(saddr));
}

// cp.async helpers
__device__ __forceinline__ void cpa16(uint32_t saddr, const void* gptr) {
    asm volatile("cp.async.ca.shared.global [%0], [%1], 16;" :: "r"(saddr), "l"(gptr));
}
__device__ __forceinline__ void cpa_commit() { asm volatile("cp.async.commit_group;"); }
__device__ __forceinline__ void cpa_wait0() { asm volatile("cp.async.wait_group 0;"); }

// ---------------- merged prep kernel ----------------
__global__ void __launch_bounds__(256)
prep_kernel(float* __restrict__ out, int out_size,
            const float* __restrict__ wWf, const float* __restrict__ wWb,
            const float* __restrict__ cWhhF, const float* __restrict__ cWhhB,
            const float* __restrict__ ff1W, const float* __restrict__ ff2W)
{
    const int stride = gridDim.x * blockDim.x;
    const int i0 = blockIdx.x * blockDim.x + threadIdx.x;
    const __half hz = __float2half(0.0f);
    for (int i = i0; i < out_size; i += stride) out[i] = 0.0f;
    for (size_t i = i0; i < (size_t)2 * 2 * NC_ * Hc_; i += stride) {
        (&g_ch_h[0][0][0])[i] = hz;
        (&g_ch_l[0][0][0])[i] = hz;
    }
    for (int i = i0; i < 2 * NC_ * Hc_; i += stride)
        (&g_char_c[0][0])[i] = 0.0f;
    for (int i = i0; i < 2 * 2 * B_ * Hw_; i += stride) {
        (&g_wh_h[0][0][0])[i] = hz;
        (&g_wh_l[0][0][0])[i] = hz;
    }
    for (int i = i0; i < 2 * B_ * Hw_; i += stride)
        (&g_word_c[0][0])[i] = 0.0f;
    const int per = 4 * Hw_ * Kp_;
    for (int idx = i0; idx < 2 * per; idx += stride) {
        int dir = idx / per;
        int r = idx - dir * per;
        int n = r / Kp_, k = r - n * Kp_;
        const float* Wsrc = dir ? wWb : wWf;
        float v = (k < D_) ? Wsrc[(size_t)n * D_ + k] : 0.0f;
        split2h(v, g_wih_h[dir][r], g_wih_l[dir][r]);
    }
    const int cn = 4 * Hc_ * Hc_;
    for (int i = i0; i < cn; i += stride) {
        split2h(cWhhF[i], g_cwhh_h[0][i], g_cwhh_l[0][i]);
        split2h(cWhhB[i], g_cwhh_h[1][i], g_cwhh_l[1][i]);
    }
    for (int i = i0; i < Hw_ * 2 * Hw_; i += stride)
        split2h(ff1W[i], g_ff1w_h[i], g_ff1w_l[i]);
    for (int i = i0; i < T_ * Hw_; i += stride)
        split2h(ff2W[i], g_ff2w_h[i], g_ff2w_l[i]);
}

__global__ void __launch_bounds__(256)
char_vocab_proj(const float* __restrict__ emb,
                const float* __restrict__ WihF, const float* __restrict__ bihF,
                const float* __restrict__ bhhF,
                const float* __restrict__ WihB, const float* __restrict__ bihB,
                const float* __restrict__ bhhB)
{
    int dir = blockIdx.x >> 7;
    int cid = blockIdx.x & 127;
    const float* Wih = dir ? WihB : WihF;
    const float* bih = dir ? bihB : bihF;
    const float* bhh = dir ? bhhB : bhhF;
    __shared__ float e[Ec_];
    if (threadIdx.x < Ec_) e[threadIdx.x] = emb[cid * Ec_ + threadIdx.x];
    __syncthreads();
    for (int n = threadIdx.x; n < 4 * Hc_; n += 256) {
        float s = bih[n] + bhh[n];
        const float* wr = &Wih[(size_t)n * Ec_];
#pragma unroll 8
        for (int k = 0; k < Ec_; k++) s += e[k] * wr[k];
        g_cproj[dir][cid * 4 * Hc_ + n] = s;
    }
}

__global__ void __launch_bounds__(256)
build_x_kernel(const int* __restrict__ wid, const int* __restrict__ cap,
               const float* __restrict__ wemb, const float* __restrict__ cemb)
{
    int idx = blockIdx.x * blockDim.x + threadIdx.x;
    if (idx >= NC_ * Kp_) return;
    int d = idx % Kp_;
    int sb = idx / Kp_;
    int s = sb / B_, b = sb % B_;
    float v = 0.0f;
    if (d < E_) {
        v = wemb[(size_t)wid[s * B_ + b] * E_ + d];
    } else if (d < E_ + 2 * Hc_) {
        int j = d - E_;
        int n = b * S_ + s;
        size_t off = (j < Hc_) ? ((size_t)n * Hc_ + j) : ((size_t)n * Hc_ + (j - Hc_));
        int dd = (j < Hc_) ? 0 : 1;
        v = __half2float(g_ch_h[dd][0][off]) + __half2float(g_ch_l[dd][0][off]);
    } else if (d == E_ + 2 * Hc_) {
        v = cemb[cap[s * B_ + b]];
    }
    split2h(v, g_x_h[idx], g_x_l[idx]);
}

// ---------------- 3xFP16 GEMM (cp.async + ldmatrix) ------------------------------
#define GEH_PITCH 40
#define GEH_PLANE (128 * GEH_PITCH)   // 5120 halves
#define GEH_STAGE (4 * GEH_PLANE)     // 20480 halves = 40 KB
__global__ void __launch_bounds__(256, 2)
hmma_gemm(const __half* __restrict__ AH, const __half* __restrict__ AL,
          const __half* __restrict__ WH, const __half* __restrict__ WL,
          const float* __restrict__ b1, const float* __restrict__ b2,
          float* __restrict__ C, __half* __restrict__ Ch, __half* __restrict__ Cl,
          int M, int N, int K, int act)
{
    extern __shared__ __align__(16) __half smh[];
    const int tid = threadIdx.x;
    const int w = tid >> 5, l = tid & 31;
    const int wm = w & 1, wn = w >> 1;
    const int g = l >> 2, tg = l & 3;
    const int sub = l >> 3, ri = l & 7;
    const int a_ro = ((sub & 1) << 3) + ri;
    const int a_ko = (sub >> 1) << 3;
    const int b_ro = ((sub >> 1) << 3) + ri;
    const int b_ko = (sub & 1) << 3;
    const int m0 = blockIdx.y * 128, n0 = blockIdx.x * 128;
    const uint32_t sbase = (uint32_t)__cvta_generic_to_shared(smh);

    float acc[4][4][4] = {};
    const int KT = K >> 5;

    auto issue = [&](int kt, int stage) {
        uint32_t sa = sbase + (uint32_t)(stage * GEH_STAGE) * 2;
#pragma unroll
        for (int q = 0; q < 8; q++) {
            int i = tid + q * 256;
            int p = i >> 9;
            int r = (i & 511) >> 2;
            int ch = i & 3;
            const __half* gp = (p == 0) ? AH : (p == 1) ? AL : (p == 2) ? WH : WL;
            int row = (p < 2) ? (m0 + r) : (n0 + r);
            if (p >= 2 && row >= N) row = N - 1;   // clamp; never stored
            size_t go = (size_t)row * K + kt * 32 + ch * 8;
            cpa16(sa + (uint32_t)(p * GEH_PLANE + r * GEH_PITCH + ch * 8) * 2, gp + go);
        }
        cpa_commit();
    };

    issue(0, 0);
    for (int kt = 0; kt < KT; kt++) {
        cpa_wait0();
        __syncthreads();
        if (kt + 1 < KT) issue(kt + 1, (kt + 1) & 1);
        uint32_t stA  = sbase + (uint32_t)((kt & 1) * GEH_STAGE) * 2;
        uint32_t stAl = stA + (uint32_t)GEH_PLANE * 2;
        uint32_t stW  = stA + (uint32_t)(2 * GEH_PLANE) * 2;
        uint32_t stWl = stA + (uint32_t)(3 * GEH_PLANE) * 2;
#pragma unroll
        for (int ks = 0; ks < 2; ks++) {
            unsigned ah[4][4], al[4][4], bh2[2][4], bl2[2][4];
#pragma unroll
            for (int mi = 0; mi < 4; mi++) {
                uint32_t off = (uint32_t)((wm * 64 + mi * 16 + a_ro) * GEH_PITCH
                                          + ks * 16 + a_ko) * 2;
                ldm_x4(ah[mi], stA + off);
                ldm_x4(al[mi], stAl + off);
            }
#pragma unroll
            for (int nq = 0; nq < 2; nq++) {
                uint32_t off = (uint32_t)((wn * 32 + nq * 16 + b_ro) * GEH_PITCH
                                          + ks * 16 + b_ko) * 2;
                ldm_x4(bh2[nq], stW + off);
                ldm_x4(bl2[nq], stWl + off);
            }
#pragma unroll
            for (int mi = 0; mi < 4; mi++)
#pragma unroll
                for (int nq = 0; nq < 2; nq++) {
                    mma3h(acc[mi][2 * nq],     ah[mi], al[mi], bh2[nq],     bl2[nq]);
                    mma3h(acc[mi][2 * nq + 1], ah[mi], al[mi], bh2[nq] + 2, bl2[nq] + 2);
                }
        }
    }
#pragma unroll
    for (int mi = 0; mi < 4; mi++) {
#pragma unroll
        for (int ni = 0; ni < 4; ni++) {
            int m = m0 + wm * 64 + mi * 16 + g;
            int n = n0 + wn * 32 + ni * 8 + 2 * tg;
#pragma unroll
            for (int q = 0; q < 4; q++) {
                int mm = m + (q >> 1) * 8;
                int nn = n + (q & 1);
                if (nn >= N) continue;
                float v = acc[mi][ni][q];
                if (b1) v += b1[nn];
                if (b2) v += b2[nn];
                if (act == 1) v = tanhf(v);
                size_t off = (size_t)mm * N + nn;
                if (Ch) split2h(v, Ch[off], Cl[off]);
                else C[off] = v;
            }
        }
    }
}

// ---------------- fused char LSTM step: M=64, N=128, K=128 (fp16, 3 blocks/SM) ---
#define CSH_APLANE (64 * 40)
#define CSH_WPLANE (128 * 40)
#define CSH_STAGE  (2 * CSH_APLANE + 2 * CSH_WPLANE)   // 15360 halves = 30 KB
__global__ void __launch_bounds__(256, 3)
char_step_kernel(const int* __restrict__ cin, int t)
{
    const int dir = blockIdx.z;
    const int t_eff = dir ? (W_ - 1 - t) : t;
    const __half* hpH = g_ch_h[dir][t & 1];
    const __half* hpL = g_ch_l[dir][t & 1];
    __half* hnH = g_ch_h[dir][(t + 1) & 1];
    __half* hnL = g_ch_l[dir][(t + 1) & 1];
    float* cst = g_char_c[dir];
    const __half* WhS = g_cwhh_h[dir];
    const __half* WlS = g_cwhh_l[dir];
    const float* proj = g_cproj[dir];

    extern __shared__ __align__(16) __half smh[];
    float (*zb)[132] = (float(*)[132])smh;
    const uint32_t sbase = (uint32_t)__cvta_generic_to_shared(smh);

    const int tid = threadIdx.x;
    const int w = tid >> 5, l = tid & 31;
    const int wm = w & 1, wn = w >> 1;
    const int g = l >> 2, tg = l & 3;
    const int sub = l >> 3, ri = l & 7;
    const int a_ro = ((sub & 1) << 3) + ri;
    const int a_ko = (sub >> 1) << 3;
    const int b_ro = ((sub >> 1) << 3) + ri;
    const int b_ko = (sub & 1) << 3;
    const int j0 = blockIdx.x * 32;
    const int m0 = blockIdx.y * 64;

    float acc[2][4][4] = {};

    auto issue = [&](int kt, int stage) {
        uint32_t sa = sbase + (uint32_t)(stage * CSH_STAGE) * 2;
#pragma unroll
        for (int q = 0; q < 6; q++) {
            int i = tid + q * 256;
            if (i < 512) {
                int p = i >> 8;
                int r = (i & 255) >> 2;
                int ch = i & 3;
                const __half* gp = p ? hpL : hpH;
                size_t go = (size_t)(m0 + r) * Hc_ + kt * 32 + ch * 8;
                cpa16(sa + (uint32_t)(p * CSH_APLANE + r * 40 + ch * 8) * 2, gp + go);
            } else {
                int j = i - 512;
                int p = j >> 9;
                int r = (j & 511) >> 2;
                int ch = j & 3;
                const __half* gp = p ? WlS : WhS;
                int wr = (r >> 5) * Hc_ + j0 + (r & 31);
                size_t go = (size_t)wr * Hc_ + kt * 32 + ch * 8;
                cpa16(sa + (uint32_t)(2 * CSH_APLANE + p * CSH_WPLANE + r * 40 + ch * 8) * 2,
                      gp + go);
            }
        }
        cpa_commit();
    };

    issue(0, 0);
#pragma unroll 1
    for (int kt = 0; kt < 4; kt++) {
        cpa_wait0();
        __syncthreads();
        if (kt + 1 < 4) issue(kt + 1, (kt + 1) & 1);
        uint32_t stA  = sbase + (uint32_t)((kt & 1) * CSH_STAGE) * 2;
        uint32_t stAl = stA + (uint32_t)CSH_APLANE * 2;
        uint32_t stW  = stA + (uint32_t)(2 * CSH_APLANE) * 2;
        uint32_t stWl = stW + (uint32_t)CSH_WPLANE * 2;
#pragma unroll
        for (int ks = 0; ks < 2; ks++) {
            unsigned ah[2][4], al[2][4], bh2[2][4], bl2[2][4];
#pragma unroll
            for (int mi = 0; mi < 2; mi++) {
                uint32_t off = (uint32_t)((wm * 32 + mi * 16 + a_ro) * 40
                                          + ks * 16 + a_ko) * 2;
                ldm_x4(ah[mi], stA + off);
                ldm_x4(al[mi], stAl + off);
            }
#pragma unroll
            for (int nq = 0; nq < 2; nq++) {
                uint32_t off = (uint32_t)((wn * 32 + nq * 16 + b_ro) * 40
                                          + ks * 16 + b_ko) * 2;
                ldm_x4(bh2[nq], stW + off);
                ldm_x4(bl2[nq], stWl + off);
            }
#pragma unroll
            for (int mi = 0; mi < 2; mi++)
#pragma unroll
                for (int nq = 0; nq < 2; nq++) {
                    mma3h(acc[mi][2 * nq],     ah[mi], al[mi], bh2[nq],     bl2[nq]);
                    mma3h(acc[mi][2 * nq + 1], ah[mi], al[mi], bh2[nq] + 2, bl2[nq] + 2);
                }
        }
    }
    __syncthreads();
#pragma unroll
    for (int mi = 0; mi < 2; mi++) {
#pragma unroll
        for (int ni = 0; ni < 4; ni++) {
            int row = wm * 32 + mi * 16 + g;
            int col = wn * 32 + ni * 8 + 2 * tg;
            zb[row][col]         = acc[mi][ni][0];
            zb[row][col + 1]     = acc[mi][ni][1];
            zb[row + 8][col]     = acc[mi][ni][2];
            zb[row + 8][col + 1] = acc[mi][ni][3];
        }
    }
    __syncthreads();
    for (int idx = tid; idx < 64 * 32; idx += 256) {
        int ml = idx >> 5, jj = idx & 31;
        int j = j0 + jj;
        int m = m0 + ml;
        int cid = cin[m * W_ + t_eff];
        const float* pr = &proj[(size_t)cid * 4 * Hc_];
        float zi = zb[ml][jj]      + pr[j];
        float zf = zb[ml][32 + jj] + pr[Hc_ + j];
        float zg = zb[ml][64 + jj] + pr[2 * Hc_ + j];
        float zo = zb[ml][96 + jj] + pr[3 * Hc_ + j];
        size_t off = (size_t)m * Hc_ + j;
        float c = cst[off];
        c = sigf(zf) * c + sigf(zi) * tanhf(zg);
        cst[off] = c;
        float hv = sigf(zo) * tanhf(c);
        split2h(hv, hnH[off], hnL[off]);
    }
}

// ---------------- persistent word BiLSTM: j-tile 4, 256 blocks, 2/SM -------------
#define WPH_WPITCH 520
#define WPH_WPLANE (16 * WPH_WPITCH)   // 8320 halves
#define WPH_APITCH 72
#define WPH_APLANE (64 * WPH_APITCH)   // 4608 halves
#define WPH_ASTAGE (2 * WPH_APLANE)    // 9216 halves (hi+lo)
#define WPH_HALVES (2 * WPH_WPLANE + 2 * WPH_ASTAGE)   // 35072
#define WP_ZB  (64 * 20)
#define WP_XS  (64 * 20)
#define WP_SMEM_BYTES (WPH_HALVES * 2 + (WP_ZB + WP_XS) * 4)
__device__ __forceinline__ void grid_bar_dir(int dir) {
    __syncthreads();
    if (threadIdx.x == 0) {
        __threadfence();
        int gen = g_bar_gen[dir];
        if (atomicAdd((int*)&g_bar_count[dir], 1) == 127) {
            g_bar_count[dir] = 0;
            __threadfence();
            g_bar_gen[dir] = gen + 1;
        } else {
            while (g_bar_gen[dir] == gen) __nanosleep(20);
            __threadfence();
        }
    }
    __syncthreads();
}

__global__ void __launch_bounds__(256, 2)
word_persistent(const float* __restrict__ WhhF, const float* __restrict__ WhhB)
{
    extern __shared__ __align__(16) __half smh[];
    __half* Wh = smh;
    __half* Wl = smh + WPH_WPLANE;
    float* zbf = (float*)(smh + WPH_HALVES);
    float (*zb)[20] = (float(*)[20])zbf;
    float* xs = zbf + WP_ZB;
    const uint32_t sbase = (uint32_t)__cvta_generic_to_shared(smh);
    const uint32_t sWl = sbase + (uint32_t)WPH_WPLANE * 2;
    const uint32_t ab_sa = sbase + (uint32_t)(2 * WPH_WPLANE) * 2;
    const uint32_t xs_sa = sbase + (uint32_t)WPH_HALVES * 2 + (uint32_t)WP_ZB * 4;

    const int dir = blockIdx.x >> 7;
    const int jb = blockIdx.x & 127;
    const int j0 = jb * 4;
    const int tid = threadIdx.x;
    const int w = tid >> 5, l = tid & 31;
    const int wm = w & 3, wn = w >> 2;   // wn in {0,1}: 8 N-cols each
    const int g = l >> 2, tg = l & 3;
    const int sub = l >> 3, ri = l & 7;
    const int a_ro = ((sub & 1) << 3) + ri;
    const int a_ko = (sub >> 1) << 3;
    const int b_row = l & 7;
    const int b_kh = (l >> 3) & 1;

    const float* Whh = dir ? WhhB : WhhF;
    // weight slice: 16 rows (4 gates x 4 j) x 512 k, split into hi/lo
    for (int i = tid; i < 16 * 512; i += 256) {
        int rr = i >> 9, k = i & 511;
        int wr = (rr >> 2) * Hw_ + j0 + (rr & 3);
        split2h(Whh[(size_t)wr * Hw_ + k], Wh[rr * WPH_WPITCH + k], Wl[rr * WPH_WPITCH + k]);
    }
    __syncthreads();

    const float* xbase = g_wxproj[dir];
    float* cst = g_word_c[dir];

    for (int t = 0; t < S_; t++) {
        const int s = dir ? (S_ - 1 - t) : t;
        const __half* hpH = g_wh_h[dir][t & 1];
        const __half* hpL = g_wh_l[dir][t & 1];
        __half* hnH = g_wh_h[dir][(t + 1) & 1];
        __half* hnL = g_wh_l[dir][(t + 1) & 1];

        auto issueA = [&](int ko, int stage) {
            uint32_t sa = ab_sa + (uint32_t)(stage * WPH_ASTAGE) * 2;
#pragma unroll
            for (int q = 0; q < 4; q++) {
                int i = tid + q * 256;
                int p = i >> 9;
                int r = (i & 511) >> 3;
                int ch = i & 7;
                const __half* gp = p ? hpL : hpH;
                size_t go = (size_t)r * Hw_ + ko * 64 + ch * 8;
                cpa16(sa + (uint32_t)(p * WPH_APLANE + r * WPH_APITCH + ch * 8) * 2, gp + go);
            }
        };

        issueA(0, 0);
        {   // x tile: 64 b x 16 (4 gates x 4 j); one 16B load per thread
            int b = tid >> 2, gate = tid & 3;
            const float* gp = xbase + ((size_t)s * B_ + b) * 4 * Hw_ + gate * Hw_ + j0;
            cpa16(xs_sa + (uint32_t)(b * 20 + gate * 4) * 4, gp);
        }
        cpa_commit();

        float acc[4] = {};
#pragma unroll 1
        for (int ko = 0; ko < 8; ko++) {
            cpa_wait0();
            __syncthreads();
            if (ko + 1 < 8) { issueA(ko + 1, (ko + 1) & 1); cpa_commit(); }
            uint32_t stAh = ab_sa + (uint32_t)((ko & 1) * WPH_ASTAGE) * 2;
            uint32_t stAl = stAh + (uint32_t)WPH_APLANE * 2;
#pragma unroll
            for (int kc = 0; kc < 4; kc++) {
                unsigned ah[4], al[4], bh2[2], bl2[2];
                uint32_t aoff = (uint32_t)((wm * 16 + a_ro) * WPH_APITCH
                                           + kc * 16 + a_ko) * 2;
                ldm_x4(ah, stAh + aoff);
                ldm_x4(al, stAl + aoff);
                uint32_t boff = (uint32_t)((wn * 8 + b_row) * WPH_WPITCH
                                           + ko * 64 + kc * 16 + b_kh * 8) * 2;
                ldm_x2(bh2, sbase + boff);
                ldm_x2(bl2, sWl + boff);
                mma3h(acc, ah, al, bh2, bl2);
            }
        }
        {
            int row = wm * 16 + g;
            int col = wn * 8 + 2 * tg;
            zb[row][col]         = acc[0];
            zb[row][col + 1]     = acc[1];
            zb[row + 8][col]     = acc[2];
            zb[row + 8][col + 1] = acc[3];
        }
        __syncthreads();
        {   // cell: 64 b x 4 j, one elem per thread
            int b = tid >> 2, jj = tid & 3;
            int j = j0 + jj;
            const float* xr = xs + b * 20;
            float zi = zb[b][jj]      + xr[jj];
            float zf = zb[b][4 + jj]  + xr[4 + jj];
            float zg = zb[b][8 + jj]  + xr[8 + jj];
            float zo = zb[b][12 + jj] + xr[12 + jj];
            size_t off = (size_t)b * Hw_ + j;
            float c = cst[off];
            c = sigf(zf) * c + sigf(zi) * tanhf(zg);
            cst[off] = c;
            float hv = sigf(zo) * tanhf(c);
            __half hh, hl;
            split2h(hv, hh, hl);
            hnH[off] = hh; hnL[off] = hl;
            size_t eoff = ((size_t)s * B_ + b) * (2 * Hw_) + dir * Hw_ + j;
            g_enc_h[eoff] = hh; g_enc_l[eoff] = hl;
        }
        grid_bar_dir(dir);
    }
}

// ---------------- merged CRF forward + Viterbi ----------------
__global__ void __launch_bounds__(32)
crf_fwd_kernel(const float* __restrict__ trans, const float* __restrict__ start,
               const float* __restrict__ endv, float* __restrict__ out, int out_size)
{
    __shared__ float tr[T_][T_];
    __shared__ float vec[T_];
    __shared__ unsigned char bp[S_ - 1][T_];
    const int to = threadIdx.x;
    for (int i = to; i < T_ * T_; i += T_) tr[i / T_][i % T_] = trans[i];

    if (blockIdx.x < B_) {
        const int b = blockIdx.x;
        vec[to] = start[to] + g_logits[(size_t)(0 * B_ + b) * T_ + to];
        __syncthreads();
        for (int s = 1; s < S_; s++) {
            float m = -1e30f;
#pragma unroll
            for (int f = 0; f < T_; f++) m = fmaxf(m, vec[f] + tr[f][to]);
            float sum = 0.0f;
#pragma unroll
            for (int f = 0; f < T_; f++) sum += expf(vec[f] + tr[f][to] - m);
            float a = m + logf(sum) + g_logits[((size_t)s * B_ + b) * T_ + to];
            __syncthreads();
            vec[to] = a;
            __syncthreads();
        }
        float v = vec[to] + endv[to];
        float m = v;
#pragma unroll
        for (int o = 16; o > 0; o >>= 1) m = fmaxf(m, __shfl_xor_sync(0xffffffffu, m, o));
        float e = expf(v - m);
#pragma unroll
        for (int o = 16; o > 0; o >>= 1) e += __shfl_xor_sync(0xffffffffu, e, o);
        if (to == 0) g_logZ[b] = m + logf(e);
    } else {
        const int b = blockIdx.x - B_;
        vec[to] = start[to] + g_logits[(size_t)b * T_ + to];
        __syncthreads();
        for (int s = 1; s < S_; s++) {
            float best = -1e30f;
            int arg = 0;
#pragma unroll
            for (int f = 0; f < T_; f++) {
                float sc = vec[f] + tr[f][to];
                if (sc > best) { best = sc; arg = f; }
            }
            bp[s - 1][to] = (unsigned char)arg;
            float nv = best + g_logits[((size_t)s * B_ + b) * T_ + to];
            __syncthreads();
            vec[to] = nv;
            __syncthreads();
        }
        if (to == 0) {
            float best = -1e30f;
            int last = 0;
            for (int f = 0; f < T_; f++) {
                float sc = vec[f] + endv[f];
                if (sc > best) { best = sc; last = f; }
            }
            int tag = last;
            int base = 1 + b * S_;
            if (base + S_ - 1 < out_size) out[base + S_ - 1] = (float)tag;
            for (int s = S_ - 2; s >= 0; s--) {
                tag = bp[s][tag];
                if (base + s < out_size) out[base + s] = (float)tag;
            }
        }
    }
}

__global__ void __launch_bounds__(64)
crf_loss_kernel(const int* __restrict__ tags, const float* __restrict__ trans,
                const float* __restrict__ start, const float* __restrict__ endv,
                float* __restrict__ out, int out_size)
{
    __shared__ float red[B_];
    const int b = threadIdx.x;
    int prev = tags[0 * B_ + b];
    float score = start[prev];
    for (int s = 0; s < S_; s++) {
        int tg = tags[s * B_ + b];
        score += g_logits[((size_t)s * B_ + b) * T_ + tg];
        if (s > 0) score += trans[prev * T_ + tg];
        prev = tg;
    }
    score += endv[prev];
    red[b] = g_logZ[b] - score;
    __syncthreads();
    if (b == 0) {
        float t = 0.0f;
        for (int i = 0; i < B_; i++) t += red[i];
        if (out_size > 0) out[0] = t;
    }
}

// ---------------- host-side orchestration ----------------
extern "C" void kernel_launch(void* const* d_in, const int* in_sizes, int n_in,
                              void* d_out, int out_size) {
    (void)in_sizes; (void)n_in;
    const int*   word_inputs = (const int*)d_in[0];
    const int*   char_inputs = (const int*)d_in[1];
    const int*   cap_inputs  = (const int*)d_in[2];
    const int*   tag_inputs  = (const int*)d_in[3];
    const float* word_emb    = (const float*)d_in[4];
    const float* cap_emb     = (const float*)d_in[5];
    const float* char_emb    = (const float*)d_in[6];
    const float* cWih_f = (const float*)d_in[7];
    const float* cWhh_f = (const float*)d_in[8];
    const float* cbih_f = (const float*)d_in[9];
    const float* cbhh_f = (const float*)d_in[10];
    const float* cWih_b = (const float*)d_in[11];
    const float* cWhh_b = (const float*)d_in[12];
    const float* cbih_b = (const float*)d_in[13];
    const float* cbhh_b = (const float*)d_in[14];
    const float* wWih_f = (const float*)d_in[15];
    const float* wWhh_f = (const float*)d_in[16];
    const float* wbih_f = (const float*)d_in[17];
    const float* wbhh_f = (const float*)d_in[18];
    const float* wWih_b = (const float*)d_in[19];
    const float* wWhh_b = (const float*)d_in[20];
    const float* wbih_b = (const float*)d_in[21];
    const float* wbhh_b = (const float*)d_in[22];
    const float* ff1_W  = (const float*)d_in[23];
    const float* ff1_b  = (const float*)d_in[24];
    const float* ff2_W  = (const float*)d_in[25];
    const float* ff2_b  = (const float*)d_in[26];
    const float* trans  = (const float*)d_in[27];
    const float* start_trans = (const float*)d_in[28];
    const float* end_trans   = (const float*)d_in[29];
    float* out = (float*)d_out;

    __half *pxh, *pxl, *pwihh, *pwihl, *pench, *pencl, *ph1h, *ph1l;
    __half *pff1h, *pff1l, *pff2h, *pff2l;
    float *pwx, *plog;
    cudaGetSymbolAddress((void**)&pxh,   g_x_h);
    cudaGetSymbolAddress((void**)&pxl,   g_x_l);
    cudaGetSymbolAddress((void**)&pwihh, g_wih_h);
    cudaGetSymbolAddress((void**)&pwihl, g_wih_l);
    cudaGetSymbolAddress((void**)&pwx,   g_wxproj);
    cudaGetSymbolAddress((void**)&pench, g_enc_h);
    cudaGetSymbolAddress((void**)&pencl, g_enc_l);
    cudaGetSymbolAddress((void**)&ph1h,  g_h1_h);
    cudaGetSymbolAddress((void**)&ph1l,  g_h1_l);
    cudaGetSymbolAddress((void**)&plog,  g_logits);
    cudaGetSymbolAddress((void**)&pff1h, g_ff1w_h);
    cudaGetSymbolAddress((void**)&pff1l, g_ff1w_l);
    cudaGetSymbolAddress((void**)&pff2h, g_ff2w_h);
    cudaGetSymbolAddress((void**)&pff2l, g_ff2w_l);

    const size_t wih_per = (size_t)4 * Hw_ * Kp_;
    const size_t wx_per = (size_t)NC_ * 4 * Hw_;

    const int ge_smem = 2 * GEH_STAGE * 2;     // 80 KB
    const int ch_smem = 2 * CSH_STAGE * 2;     // 60 KB (3 blocks/SM)
    const int wp_smem = WP_SMEM_BYTES;         // ~78.5 KB (2 blocks/SM)
    cudaFuncSetAttribute(hmma_gemm, cudaFuncAttributeMaxDynamicSharedMemorySize, ge_smem);
    cudaFuncSetAttribute(char_step_kernel, cudaFuncAttributeMaxDynamicSharedMemorySize, ch_smem);
    cudaFuncSetAttribute(word_persistent, cudaFuncAttributeMaxDynamicSharedMemorySize, wp_smem);

    // 0) merged prep + vocab proj
    prep_kernel<<<2048, 256>>>(out, out_size, wWih_f, wWih_b, cWhh_f, cWhh_b, ff1_W, ff2_W);
    char_vocab_proj<<<2 * VC_, 256>>>(char_emb, cWih_f, cbih_f, cbhh_f, cWih_b, cbih_b, cbhh_b);

    // 1) char BiLSTM (M=64 tiles, 3 blocks/SM)
    for (int t = 0; t < W_; t++)
        char_step_kernel<<<dim3(4, NC_ / 64, 2), 256, ch_smem>>>(char_inputs, t);

    // 2) build padded word input (fp16 planes)
    build_x_kernel<<<(NC_ * Kp_ + 255) / 256, 256>>>(word_inputs, cap_inputs, word_emb, cap_emb);

    // 3) word input projections
    hmma_gemm<<<dim3(4 * Hw_ / 128, NC_ / 128), 256, ge_smem>>>(
        pxh, pxl, pwihh, pwihl, wbih_f, wbhh_f, pwx, nullptr, nullptr, NC_, 4 * Hw_, Kp_, 0);
    hmma_gemm<<<dim3(4 * Hw_ / 128, NC_ / 128), 256, ge_smem>>>(
        pxh, pxl, pwihh + wih_per, pwihl + wih_per, wbih_b, wbhh_b,
        pwx + wx_per, nullptr, nullptr, NC_, 4 * Hw_, Kp_, 0);

    // 4) persistent word BiLSTM (256 blocks, j-tile 4, 2 blocks/SM)
    word_persistent<<<256, 256, wp_smem>>>(wWhh_f, wWhh_b);

    // 5) feed-forward head
    hmma_gemm<<<dim3(Hw_ / 128, NC_ / 128), 256, ge_smem>>>(
        pench, pencl, pff1h, pff1l, ff1_b, nullptr, nullptr, ph1h, ph1l, NC_, Hw_, 2 * Hw_, 1);
    hmma_gemm<<<dim3(1, NC_ / 128), 256, ge_smem>>>(
        ph1h, ph1l, pff2h, pff2l, ff2_b, nullptr, plog, nullptr, nullptr, NC_, T_, Hw_, 0);

    // 6) CRF forward + Viterbi, then loss
    crf_fwd_kernel<<<2 * B_, T_>>>(trans, start_trans, end_trans, out, out_size);
    crf_loss_kernel<<<1, B_>>>(tag_inputs, trans, start_trans, end_trans, out, out_size);
}

// round 15
// speedup vs baseline: 1.0946x; 1.0946x over previous
#include <cuda_runtime.h>
#include <cuda_fp16.h>
#include <stdint.h>
#include <math.h>

// ---------------- problem constants ----------------
#define S_   256
#define B_   64
#define W_   16
#define Ec_  64
#define Hc_  128
#define E_   300
#define Hw_  512
#define T_   32
#define D_   557
#define Kp_  576
#define NC_  (B_ * S_)
#define VC_  128

// ---------------- scratch: fp16 hi/lo planes for all MMA operands ----------------
__device__ __align__(16) __half g_ch_h[2][2][NC_ * Hc_];
__device__ __align__(16) __half g_ch_l[2][2][NC_ * Hc_];
__device__ float g_char_c[2][NC_ * Hc_];
__device__ float g_cproj[2][VC_ * 4 * Hc_];
__device__ __align__(16) __half g_cwhh_h[2][4 * Hc_ * Hc_];
__device__ __align__(16) __half g_cwhh_l[2][4 * Hc_ * Hc_];
__device__ __align__(16) __half g_x_h[(size_t)NC_ * Kp_];
__device__ __align__(16) __half g_x_l[(size_t)NC_ * Kp_];
__device__ __align__(16) __half g_wih_h[2][4 * Hw_ * Kp_];
__device__ __align__(16) __half g_wih_l[2][4 * Hw_ * Kp_];
__device__ float g_wxproj[2][(size_t)NC_ * 4 * Hw_];
__device__ __align__(16) __half g_wh_h[2][2][B_ * Hw_];
__device__ __align__(16) __half g_wh_l[2][2][B_ * Hw_];
__device__ float g_word_c[2][B_ * Hw_];
__device__ __align__(16) __half g_enc_h[(size_t)NC_ * 2 * Hw_];
__device__ __align__(16) __half g_enc_l[(size_t)NC_ * 2 * Hw_];
__device__ __align__(16) __half g_h1_h[(size_t)NC_ * Hw_];
__device__ __align__(16) __half g_h1_l[(size_t)NC_ * Hw_];
__device__ __align__(16) __half g_ff1w_h[Hw_ * 2 * Hw_];
__device__ __align__(16) __half g_ff1w_l[Hw_ * 2 * Hw_];
__device__ __align__(16) __half g_ff2w_h[T_ * Hw_];
__device__ __align__(16) __half g_ff2w_l[T_ * Hw_];
__device__ float g_logits[NC_ * T_];
__device__ float g_logZ[B_];
__device__ volatile int g_bar_count[2];
__device__ volatile int g_bar_gen[2];

__device__ __forceinline__ float sigf(float x) { return 1.0f / (1.0f + expf(-x)); }

__device__ __forceinline__ void split2h(float v, __half& h, __half& l) {
    __half hh = __float2half_rn(v);
    h = hh;
    l = __float2half_rn(v - __half2float(hh));
}

// fp16 m16n8k16 mma, fp32 accumulate
__device__ __forceinline__ void mma16(float* c, const unsigned* a, const unsigned* b) {
    asm volatile(
        "mma.sync.aligned.m16n8k16.row.col.f32.f16.f16.f32 "
        "{%0,%1,%2,%3}, {%4,%5,%6,%7}, {%8,%9}, {%0,%1,%2,%3};"
        : "+f"(c[0]), "+f"(c[1]), "+f"(c[2]), "+f"(c[3])
        : "r"(a[0]), "r"(a[1]), "r"(a[2]), "r"(a[3]), "r"(b[0]), "r"(b[1]));
}
__device__ __forceinline__ void mma3h(float* c, const unsigned* ah, const unsigned* al,
                                      const unsigned* bh, const unsigned* bl) {
    mma16(c, al, bh);
    mma16(c, ah, bl);
    mma16(c, ah, bh);
}

// warp-collective ldmatrix
__device__ __forceinline__ void ldm_x4(unsigned* r, uint32_t saddr) {
    asm volatile("ldmatrix.sync.aligned.m8n8.x4.shared.b16 {%0,%1,%2,%3}, [%4];"
        : "=r"(r[0]), "=r"(r[1]), "=r"(r[2]), "=r"(r[3]) : "r"(saddr));
}

// cp.async helpers
__device__ __forceinline__ void cpa16(uint32_t saddr, const void* gptr) {
    asm volatile("cp.async.ca.shared.global [%0], [%1], 16;" :: "r"(saddr), "l"(gptr));
}
__device__ __forceinline__ void cpa_commit() { asm volatile("cp.async.commit_group;"); }
__device__ __forceinline__ void cpa_wait0() { asm volatile("cp.async.wait_group 0;"); }

// ---------------- merged prep kernel ----------------
__global__ void __launch_bounds__(256)
prep_kernel(float* __restrict__ out, int out_size,
            const float* __restrict__ wWf, const float* __restrict__ wWb,
            const float* __restrict__ cWhhF, const float* __restrict__ cWhhB,
            const float* __restrict__ ff1W, const float* __restrict__ ff2W)
{
    const int stride = gridDim.x * blockDim.x;
    const int i0 = blockIdx.x * blockDim.x + threadIdx.x;
    const __half hz = __float2half(0.0f);
    for (int i = i0; i < out_size; i += stride) out[i] = 0.0f;
    for (size_t i = i0; i < (size_t)2 * 2 * NC_ * Hc_; i += stride) {
        (&g_ch_h[0][0][0])[i] = hz;
        (&g_ch_l[0][0][0])[i] = hz;
    }
    for (int i = i0; i < 2 * NC_ * Hc_; i += stride)
        (&g_char_c[0][0])[i] = 0.0f;
    for (int i = i0; i < 2 * 2 * B_ * Hw_; i += stride) {
        (&g_wh_h[0][0][0])[i] = hz;
        (&g_wh_l[0][0][0])[i] = hz;
    }
    for (int i = i0; i < 2 * B_ * Hw_; i += stride)
        (&g_word_c[0][0])[i] = 0.0f;
    const int per = 4 * Hw_ * Kp_;
    for (int idx = i0; idx < 2 * per; idx += stride) {
        int dir = idx / per;
        int r = idx - dir * per;
        int n = r / Kp_, k = r - n * Kp_;
        const float* Wsrc = dir ? wWb : wWf;
        float v = (k < D_) ? Wsrc[(size_t)n * D_ + k] : 0.0f;
        split2h(v, g_wih_h[dir][r], g_wih_l[dir][r]);
    }
    const int cn = 4 * Hc_ * Hc_;
    for (int i = i0; i < cn; i += stride) {
        split2h(cWhhF[i], g_cwhh_h[0][i], g_cwhh_l[0][i]);
        split2h(cWhhB[i], g_cwhh_h[1][i], g_cwhh_l[1][i]);
    }
    for (int i = i0; i < Hw_ * 2 * Hw_; i += stride)
        split2h(ff1W[i], g_ff1w_h[i], g_ff1w_l[i]);
    for (int i = i0; i < T_ * Hw_; i += stride)
        split2h(ff2W[i], g_ff2w_h[i], g_ff2w_l[i]);
}

__global__ void __launch_bounds__(256)
char_vocab_proj(const float* __restrict__ emb,
                const float* __restrict__ WihF, const float* __restrict__ bihF,
                const float* __restrict__ bhhF,
                const float* __restrict__ WihB, const float* __restrict__ bihB,
                const float* __restrict__ bhhB)
{
    int dir = blockIdx.x >> 7;
    int cid = blockIdx.x & 127;
    const float* Wih = dir ? WihB : WihF;
    const float* bih = dir ? bihB : bihF;
    const float* bhh = dir ? bhhB : bhhF;
    __shared__ float e[Ec_];
    if (threadIdx.x < Ec_) e[threadIdx.x] = emb[cid * Ec_ + threadIdx.x];
    __syncthreads();
    for (int n = threadIdx.x; n < 4 * Hc_; n += 256) {
        float s = bih[n] + bhh[n];
        const float* wr = &Wih[(size_t)n * Ec_];
#pragma unroll 8
        for (int k = 0; k < Ec_; k++) s += e[k] * wr[k];
        g_cproj[dir][cid * 4 * Hc_ + n] = s;
    }
}

__global__ void __launch_bounds__(256)
build_x_kernel(const int* __restrict__ wid, const int* __restrict__ cap,
               const float* __restrict__ wemb, const float* __restrict__ cemb)
{
    int idx = blockIdx.x * blockDim.x + threadIdx.x;
    if (idx >= NC_ * Kp_) return;
    int d = idx % Kp_;
    int sb = idx / Kp_;
    int s = sb / B_, b = sb % B_;
    float v = 0.0f;
    if (d < E_) {
        v = wemb[(size_t)wid[s * B_ + b] * E_ + d];
    } else if (d < E_ + 2 * Hc_) {
        int j = d - E_;
        int n = b * S_ + s;
        size_t off = (j < Hc_) ? ((size_t)n * Hc_ + j) : ((size_t)n * Hc_ + (j - Hc_));
        int dd = (j < Hc_) ? 0 : 1;
        v = __half2float(g_ch_h[dd][0][off]) + __half2float(g_ch_l[dd][0][off]);
    } else if (d == E_ + 2 * Hc_) {
        v = cemb[cap[s * B_ + b]];
    }
    split2h(v, g_x_h[idx], g_x_l[idx]);
}

// ---------------- 3xFP16 GEMM: tile M=64, N=128, K=32/stage (3 blocks/SM) --------
#define G64_APLANE (64 * 40)
#define G64_WPLANE (128 * 40)
#define G64_STAGE  (2 * G64_APLANE + 2 * G64_WPLANE)   // 15360 halves = 30 KB
__global__ void __launch_bounds__(256, 3)
hmma_gemm(const __half* __restrict__ AH, const __half* __restrict__ AL,
          const __half* __restrict__ WH, const __half* __restrict__ WL,
          const float* __restrict__ b1, const float* __restrict__ b2,
          float* __restrict__ C, __half* __restrict__ Ch, __half* __restrict__ Cl,
          int M, int N, int K, int act)
{
    extern __shared__ __align__(16) __half smh[];
    const int tid = threadIdx.x;
    const int w = tid >> 5, l = tid & 31;
    const int wm = w & 1, wn = w >> 1;
    const int g = l >> 2, tg = l & 3;
    const int sub = l >> 3, ri = l & 7;
    const int a_ro = ((sub & 1) << 3) + ri;
    const int a_ko = (sub >> 1) << 3;
    const int b_ro = ((sub >> 1) << 3) + ri;
    const int b_ko = (sub & 1) << 3;
    const int m0 = blockIdx.y * 64, n0 = blockIdx.x * 128;
    const uint32_t sbase = (uint32_t)__cvta_generic_to_shared(smh);

    float acc[2][4][4] = {};
    const int KT = K >> 5;

    auto issue = [&](int kt, int stage) {
        uint32_t sa = sbase + (uint32_t)(stage * G64_STAGE) * 2;
#pragma unroll
        for (int q = 0; q < 6; q++) {
            int i = tid + q * 256;        // 0..1535
            if (i < 512) {
                int p = i >> 8;
                int r = (i & 255) >> 2;
                int ch = i & 3;
                const __half* gp = p ? AL : AH;
                size_t go = (size_t)(m0 + r) * K + kt * 32 + ch * 8;
                cpa16(sa + (uint32_t)(p * G64_APLANE + r * 40 + ch * 8) * 2, gp + go);
            } else {
                int j = i - 512;          // 0..1023
                int p = j >> 9;
                int r = (j & 511) >> 2;
                int ch = j & 3;
                const __half* gp = p ? WL : WH;
                int row = n0 + r;
                if (row >= N) row = N - 1;   // clamp; never stored
                size_t go = (size_t)row * K + kt * 32 + ch * 8;
                cpa16(sa + (uint32_t)(2 * G64_APLANE + p * G64_WPLANE + r * 40 + ch * 8) * 2,
                      gp + go);
            }
        }
        cpa_commit();
    };

    issue(0, 0);
    for (int kt = 0; kt < KT; kt++) {
        cpa_wait0();
        __syncthreads();
        if (kt + 1 < KT) issue(kt + 1, (kt + 1) & 1);
        uint32_t stA  = sbase + (uint32_t)((kt & 1) * G64_STAGE) * 2;
        uint32_t stAl = stA + (uint32_t)G64_APLANE * 2;
        uint32_t stW  = stA + (uint32_t)(2 * G64_APLANE) * 2;
        uint32_t stWl = stW + (uint32_t)G64_WPLANE * 2;
#pragma unroll
        for (int ks = 0; ks < 2; ks++) {
            unsigned ah[2][4], al[2][4], bh2[2][4], bl2[2][4];
#pragma unroll
            for (int mi = 0; mi < 2; mi++) {
                uint32_t off = (uint32_t)((wm * 32 + mi * 16 + a_ro) * 40
                                          + ks * 16 + a_ko) * 2;
                ldm_x4(ah[mi], stA + off);
                ldm_x4(al[mi], stAl + off);
            }
#pragma unroll
            for (int nq = 0; nq < 2; nq++) {
                uint32_t off = (uint32_t)((wn * 32 + nq * 16 + b_ro) * 40
                                          + ks * 16 + b_ko) * 2;
                ldm_x4(bh2[nq], stW + off);
                ldm_x4(bl2[nq], stWl + off);
            }
#pragma unroll
            for (int mi = 0; mi < 2; mi++)
#pragma unroll
                for (int nq = 0; nq < 2; nq++) {
                    mma3h(acc[mi][2 * nq],     ah[mi], al[mi], bh2[nq],     bl2[nq]);
                    mma3h(acc[mi][2 * nq + 1], ah[mi], al[mi], bh2[nq] + 2, bl2[nq] + 2);
                }
        }
    }
#pragma unroll
    for (int mi = 0; mi < 2; mi++) {
#pragma unroll
        for (int ni = 0; ni < 4; ni++) {
            int m = m0 + wm * 32 + mi * 16 + g;
            int n = n0 + wn * 32 + ni * 8 + 2 * tg;
#pragma unroll
            for (int q = 0; q < 4; q++) {
                int mm = m + (q >> 1) * 8;
                int nn = n + (q & 1);
                if (nn >= N) continue;
                float v = acc[mi][ni][q];
                if (b1) v += b1[nn];
                if (b2) v += b2[nn];
                if (act == 1) v = tanhf(v);
                size_t off = (size_t)mm * N + nn;
                if (Ch) split2h(v, Ch[off], Cl[off]);
                else C[off] = v;
            }
        }
    }
}

// ---------------- fused char LSTM step: M=64, N=128, K=128 (fp16, 3 blocks/SM) ---
#define CSH_APLANE (64 * 40)
#define CSH_WPLANE (128 * 40)
#define CSH_STAGE  (2 * CSH_APLANE + 2 * CSH_WPLANE)   // 15360 halves = 30 KB
__global__ void __launch_bounds__(256, 3)
char_step_kernel(const int* __restrict__ cin, int t)
{
    const int dir = blockIdx.z;
    const int t_eff = dir ? (W_ - 1 - t) : t;
    const __half* hpH = g_ch_h[dir][t & 1];
    const __half* hpL = g_ch_l[dir][t & 1];
    __half* hnH = g_ch_h[dir][(t + 1) & 1];
    __half* hnL = g_ch_l[dir][(t + 1) & 1];
    float* cst = g_char_c[dir];
    const __half* WhS = g_cwhh_h[dir];
    const __half* WlS = g_cwhh_l[dir];
    const float* proj = g_cproj[dir];

    extern __shared__ __align__(16) __half smh[];
    float (*zb)[132] = (float(*)[132])smh;
    const uint32_t sbase = (uint32_t)__cvta_generic_to_shared(smh);

    const int tid = threadIdx.x;
    const int w = tid >> 5, l = tid & 31;
    const int wm = w & 1, wn = w >> 1;
    const int g = l >> 2, tg = l & 3;
    const int sub = l >> 3, ri = l & 7;
    const int a_ro = ((sub & 1) << 3) + ri;
    const int a_ko = (sub >> 1) << 3;
    const int b_ro = ((sub >> 1) << 3) + ri;
    const int b_ko = (sub & 1) << 3;
    const int j0 = blockIdx.x * 32;
    const int m0 = blockIdx.y * 64;

    float acc[2][4][4] = {};

    auto issue = [&](int kt, int stage) {
        uint32_t sa = sbase + (uint32_t)(stage * CSH_STAGE) * 2;
#pragma unroll
        for (int q = 0; q < 6; q++) {
            int i = tid + q * 256;
            if (i < 512) {
                int p = i >> 8;
                int r = (i & 255) >> 2;
                int ch = i & 3;
                const __half* gp = p ? hpL : hpH;
                size_t go = (size_t)(m0 + r) * Hc_ + kt * 32 + ch * 8;
                cpa16(sa + (uint32_t)(p * CSH_APLANE + r * 40 + ch * 8) * 2, gp + go);
            } else {
                int j = i - 512;
                int p = j >> 9;
                int r = (j & 511) >> 2;
                int ch = j & 3;
                const __half* gp = p ? WlS : WhS;
                int wr = (r >> 5) * Hc_ + j0 + (r & 31);
                size_t go = (size_t)wr * Hc_ + kt * 32 + ch * 8;
                cpa16(sa + (uint32_t)(2 * CSH_APLANE + p * CSH_WPLANE + r * 40 + ch * 8) * 2,
                      gp + go);
            }
        }
        cpa_commit();
    };

    issue(0, 0);
#pragma unroll 1
    for (int kt = 0; kt < 4; kt++) {
        cpa_wait0();
        __syncthreads();
        if (kt + 1 < 4) issue(kt + 1, (kt + 1) & 1);
        uint32_t stA  = sbase + (uint32_t)((kt & 1) * CSH_STAGE) * 2;
        uint32_t stAl = stA + (uint32_t)CSH_APLANE * 2;
        uint32_t stW  = stA + (uint32_t)(2 * CSH_APLANE) * 2;
        uint32_t stWl = stW + (uint32_t)CSH_WPLANE * 2;
#pragma unroll
        for (int ks = 0; ks < 2; ks++) {
            unsigned ah[2][4], al[2][4], bh2[2][4], bl2[2][4];
#pragma unroll
            for (int mi = 0; mi < 2; mi++) {
                uint32_t off = (uint32_t)((wm * 32 + mi * 16 + a_ro) * 40
                                          + ks * 16 + a_ko) * 2;
                ldm_x4(ah[mi], stA + off);
                ldm_x4(al[mi], stAl + off);
            }
#pragma unroll
            for (int nq = 0; nq < 2; nq++) {
                uint32_t off = (uint32_t)((wn * 32 + nq * 16 + b_ro) * 40
                                          + ks * 16 + b_ko) * 2;
                ldm_x4(bh2[nq], stW + off);
                ldm_x4(bl2[nq], stWl + off);
            }
#pragma unroll
            for (int mi = 0; mi < 2; mi++)
#pragma unroll
                for (int nq = 0; nq < 2; nq++) {
                    mma3h(acc[mi][2 * nq],     ah[mi], al[mi], bh2[nq],     bl2[nq]);
                    mma3h(acc[mi][2 * nq + 1], ah[mi], al[mi], bh2[nq] + 2, bl2[nq] + 2);
                }
        }
    }
    __syncthreads();
#pragma unroll
    for (int mi = 0; mi < 2; mi++) {
#pragma unroll
        for (int ni = 0; ni < 4; ni++) {
            int row = wm * 32 + mi * 16 + g;
            int col = wn * 32 + ni * 8 + 2 * tg;
            zb[row][col]         = acc[mi][ni][0];
            zb[row][col + 1]     = acc[mi][ni][1];
            zb[row + 8][col]     = acc[mi][ni][2];
            zb[row + 8][col + 1] = acc[mi][ni][3];
        }
    }
    __syncthreads();
    for (int idx = tid; idx < 64 * 32; idx += 256) {
        int ml = idx >> 5, jj = idx & 31;
        int j = j0 + jj;
        int m = m0 + ml;
        int cid = cin[m * W_ + t_eff];
        const float* pr = &proj[(size_t)cid * 4 * Hc_];
        float zi = zb[ml][jj]      + pr[j];
        float zf = zb[ml][32 + jj] + pr[Hc_ + j];
        float zg = zb[ml][64 + jj] + pr[2 * Hc_ + j];
        float zo = zb[ml][96 + jj] + pr[3 * Hc_ + j];
        size_t off = (size_t)m * Hc_ + j;
        float c = cst[off];
        c = sigf(zf) * c + sigf(zi) * tanhf(zg);
        cst[off] = c;
        float hv = sigf(zo) * tanhf(c);
        split2h(hv, hnH[off], hnL[off]);
    }
}

// ---------------- persistent word BiLSTM (R13: j-tile 8, 128 blocks) -------------
#define WPH_WPITCH 520
#define WPH_WPLANE (32 * WPH_WPITCH)   // 16640 halves
#define WPH_APITCH 72
#define WPH_APLANE (64 * WPH_APITCH)   // 4608 halves
#define WPH_ASTAGE (2 * WPH_APLANE)    // 9216 halves (hi+lo)
#define WPH_HALVES (2 * WPH_WPLANE + 2 * WPH_ASTAGE)   // 51712
#define WP_ZB  (64 * 36)
#define WP_XS  (64 * 40)
#define WP_SMEM_BYTES (WPH_HALVES * 2 + (WP_ZB + WP_XS) * 4)
__device__ __forceinline__ void grid_bar_dir(int dir) {
    __syncthreads();
    if (threadIdx.x == 0) {
        __threadfence();
        int gen = g_bar_gen[dir];
        if (atomicAdd((int*)&g_bar_count[dir], 1) == 63) {
            g_bar_count[dir] = 0;
            __threadfence();
            g_bar_gen[dir] = gen + 1;
        } else {
            while (g_bar_gen[dir] == gen) __nanosleep(20);
            __threadfence();
        }
    }
    __syncthreads();
}

__global__ void __launch_bounds__(256)
word_persistent(const float* __restrict__ WhhF, const float* __restrict__ WhhB)
{
    extern __shared__ __align__(16) __half smh[];
    __half* Wh = smh;
    __half* Wl = smh + WPH_WPLANE;
    float* zbf = (float*)(smh + WPH_HALVES);
    float (*zb)[36] = (float(*)[36])zbf;
    float* xs = zbf + WP_ZB;
    const uint32_t sbase = (uint32_t)__cvta_generic_to_shared(smh);
    const uint32_t sWl = sbase + (uint32_t)WPH_WPLANE * 2;
    const uint32_t ab_sa = sbase + (uint32_t)(2 * WPH_WPLANE) * 2;
    const uint32_t xs_sa = sbase + (uint32_t)WPH_HALVES * 2 + (uint32_t)WP_ZB * 4;

    const int dir = blockIdx.x >> 6;
    const int jb = blockIdx.x & 63;
    const int j0 = jb * 8;
    const int tid = threadIdx.x;
    const int w = tid >> 5, l = tid & 31;
    const int wm = w & 3, wn = w >> 2;
    const int g = l >> 2, tg = l & 3;
    const int sub = l >> 3, ri = l & 7;
    const int a_ro = ((sub & 1) << 3) + ri;
    const int a_ko = (sub >> 1) << 3;
    const int b_ro = ((sub >> 1) << 3) + ri;
    const int b_ko = (sub & 1) << 3;

    const float* Whh = dir ? WhhB : WhhF;
    for (int i = tid; i < 32 * 512; i += 256) {
        int rr = i >> 9, k = i & 511;
        int wr = (rr >> 3) * Hw_ + j0 + (rr & 7);
        split2h(Whh[(size_t)wr * Hw_ + k], Wh[rr * WPH_WPITCH + k], Wl[rr * WPH_WPITCH + k]);
    }
    __syncthreads();

    const float* xbase = g_wxproj[dir];
    float* cst = g_word_c[dir];

    for (int t = 0; t < S_; t++) {
        const int s = dir ? (S_ - 1 - t) : t;
        const __half* hpH = g_wh_h[dir][t & 1];
        const __half* hpL = g_wh_l[dir][t & 1];
        __half* hnH = g_wh_h[dir][(t + 1) & 1];
        __half* hnL = g_wh_l[dir][(t + 1) & 1];

        auto issueA = [&](int ko, int stage) {
            uint32_t sa = ab_sa + (uint32_t)(stage * WPH_ASTAGE) * 2;
#pragma unroll
            for (int q = 0; q < 4; q++) {
                int i = tid + q * 256;
                int p = i >> 9;
                int r = (i & 511) >> 3;
                int ch = i & 7;
                const __half* gp = p ? hpL : hpH;
                size_t go = (size_t)r * Hw_ + ko * 64 + ch * 8;
                cpa16(sa + (uint32_t)(p * WPH_APLANE + r * WPH_APITCH + ch * 8) * 2, gp + go);
            }
        };

        issueA(0, 0);
#pragma unroll
        for (int q = 0; q < 2; q++) {
            int e = tid * 2 + q;
            int b = e >> 3, subb = e & 7;
            int gate = subb >> 1, half = subb & 1;
            const float* gp = xbase + ((size_t)s * B_ + b) * 4 * Hw_ + gate * Hw_ + j0 + half * 4;
            cpa16(xs_sa + (uint32_t)(b * 40 + gate * 8 + half * 4) * 4, gp);
        }
        cpa_commit();

        float acc[2][4] = {};
#pragma unroll 1
        for (int ko = 0; ko < 8; ko++) {
            cpa_wait0();
            __syncthreads();
            if (ko + 1 < 8) { issueA(ko + 1, (ko + 1) & 1); cpa_commit(); }
            uint32_t stAh = ab_sa + (uint32_t)((ko & 1) * WPH_ASTAGE) * 2;
            uint32_t stAl = stAh + (uint32_t)WPH_APLANE * 2;
#pragma unroll
            for (int kc = 0; kc < 4; kc++) {
                unsigned ah[4], al[4], bh2[4], bl2[4];
                uint32_t aoff = (uint32_t)((wm * 16 + a_ro) * WPH_APITCH
                                           + kc * 16 + a_ko) * 2;
                ldm_x4(ah, stAh + aoff);
                ldm_x4(al, stAl + aoff);
                uint32_t boff = (uint32_t)((wn * 16 + b_ro) * WPH_WPITCH
                                           + ko * 64 + kc * 16 + b_ko) * 2;
                ldm_x4(bh2, sbase + boff);
                ldm_x4(bl2, sWl + boff);
                mma3h(acc[0], ah, al, bh2,     bl2);
                mma3h(acc[1], ah, al, bh2 + 2, bl2 + 2);
            }
        }
#pragma unroll
        for (int ni = 0; ni < 2; ni++) {
            int row = wm * 16 + g;
            int col = wn * 16 + ni * 8 + 2 * tg;
            zb[row][col]         = acc[ni][0];
            zb[row][col + 1]     = acc[ni][1];
            zb[row + 8][col]     = acc[ni][2];
            zb[row + 8][col + 1] = acc[ni][3];
        }
        __syncthreads();
        for (int idx = tid; idx < 512; idx += 256) {
            int b = idx >> 3, jj = idx & 7;
            int j = j0 + jj;
            const float* xr = xs + b * 40;
            float zi = zb[b][jj]      + xr[jj];
            float zf = zb[b][8 + jj]  + xr[8 + jj];
            float zg = zb[b][16 + jj] + xr[16 + jj];
            float zo = zb[b][24 + jj] + xr[24 + jj];
            size_t off = (size_t)b * Hw_ + j;
            float c = cst[off];
            c = sigf(zf) * c + sigf(zi) * tanhf(zg);
            cst[off] = c;
            float hv = sigf(zo) * tanhf(c);
            __half hh, hl;
            split2h(hv, hh, hl);
            hnH[off] = hh; hnL[off] = hl;
            size_t eoff = ((size_t)s * B_ + b) * (2 * Hw_) + dir * Hw_ + j;
            g_enc_h[eoff] = hh; g_enc_l[eoff] = hl;
        }
        grid_bar_dir(dir);
    }
}

// ---------------- merged CRF forward + Viterbi ----------------
__global__ void __launch_bounds__(32)
crf_fwd_kernel(const float* __restrict__ trans, const float* __restrict__ start,
               const float* __restrict__ endv, float* __restrict__ out, int out_size)
{
    __shared__ float tr[T_][T_];
    __shared__ float vec[T_];
    __shared__ unsigned char bp[S_ - 1][T_];
    const int to = threadIdx.x;
    for (int i = to; i < T_ * T_; i += T_) tr[i / T_][i % T_] = trans[i];

    if (blockIdx.x < B_) {
        const int b = blockIdx.x;
        vec[to] = start[to] + g_logits[(size_t)(0 * B_ + b) * T_ + to];
        __syncthreads();
        for (int s = 1; s < S_; s++) {
            float m = -1e30f;
#pragma unroll
            for (int f = 0; f < T_; f++) m = fmaxf(m, vec[f] + tr[f][to]);
            float sum = 0.0f;
#pragma unroll
            for (int f = 0; f < T_; f++) sum += expf(vec[f] + tr[f][to] - m);
            float a = m + logf(sum) + g_logits[((size_t)s * B_ + b) * T_ + to];
            __syncthreads();
            vec[to] = a;
            __syncthreads();
        }
        float v = vec[to] + endv[to];
        float m = v;
#pragma unroll
        for (int o = 16; o > 0; o >>= 1) m = fmaxf(m, __shfl_xor_sync(0xffffffffu, m, o));
        float e = expf(v - m);
#pragma unroll
        for (int o = 16; o > 0; o >>= 1) e += __shfl_xor_sync(0xffffffffu, e, o);
        if (to == 0) g_logZ[b] = m + logf(e);
    } else {
        const int b = blockIdx.x - B_;
        vec[to] = start[to] + g_logits[(size_t)b * T_ + to];
        __syncthreads();
        for (int s = 1; s < S_; s++) {
            float best = -1e30f;
            int arg = 0;
#pragma unroll
            for (int f = 0; f < T_; f++) {
                float sc = vec[f] + tr[f][to];
                if (sc > best) { best = sc; arg = f; }
            }
            bp[s - 1][to] = (unsigned char)arg;
            float nv = best + g_logits[((size_t)s * B_ + b) * T_ + to];
            __syncthreads();
            vec[to] = nv;
            __syncthreads();
        }
        if (to == 0) {
            float best = -1e30f;
            int last = 0;
            for (int f = 0; f < T_; f++) {
                float sc = vec[f] + endv[f];
                if (sc > best) { best = sc; last = f; }
            }
            int tag = last;
            int base = 1 + b * S_;
            if (base + S_ - 1 < out_size) out[base + S_ - 1] = (float)tag;
            for (int s = S_ - 2; s >= 0; s--) {
                tag = bp[s][tag];
                if (base + s < out_size) out[base + s] = (float)tag;
            }
        }
    }
}

__global__ void __launch_bounds__(64)
crf_loss_kernel(const int* __restrict__ tags, const float* __restrict__ trans,
                const float* __restrict__ start, const float* __restrict__ endv,
                float* __restrict__ out, int out_size)
{
    __shared__ float red[B_];
    const int b = threadIdx.x;
    int prev = tags[0 * B_ + b];
    float score = start[prev];
    for (int s = 0; s < S_; s++) {
        int tg = tags[s * B_ + b];
        score += g_logits[((size_t)s * B_ + b) * T_ + tg];
        if (s > 0) score += trans[prev * T_ + tg];
        prev = tg;
    }
    score += endv[prev];
    red[b] = g_logZ[b] - score;
    __syncthreads();
    if (b == 0) {
        float t = 0.0f;
        for (int i = 0; i < B_; i++) t += red[i];
        if (out_size > 0) out[0] = t;
    }
}

// ---------------- host-side orchestration ----------------
extern "C" void kernel_launch(void* const* d_in, const int* in_sizes, int n_in,
                              void* d_out, int out_size) {
    (void)in_sizes; (void)n_in;
    const int*   word_inputs = (const int*)d_in[0];
    const int*   char_inputs = (const int*)d_in[1];
    const int*   cap_inputs  = (const int*)d_in[2];
    const int*   tag_inputs  = (const int*)d_in[3];
    const float* word_emb    = (const float*)d_in[4];
    const float* cap_emb     = (const float*)d_in[5];
    const float* char_emb    = (const float*)d_in[6];
    const float* cWih_f = (const float*)d_in[7];
    const float* cWhh_f = (const float*)d_in[8];
    const float* cbih_f = (const float*)d_in[9];
    const float* cbhh_f = (const float*)d_in[10];
    const float* cWih_b = (const float*)d_in[11];
    const float* cWhh_b = (const float*)d_in[12];
    const float* cbih_b = (const float*)d_in[13];
    const float* cbhh_b = (const float*)d_in[14];
    const float* wWih_f = (const float*)d_in[15];
    const float* wWhh_f = (const float*)d_in[16];
    const float* wbih_f = (const float*)d_in[17];
    const float* wbhh_f = (const float*)d_in[18];
    const float* wWih_b = (const float*)d_in[19];
    const float* wWhh_b = (const float*)d_in[20];
    const float* wbih_b = (const float*)d_in[21];
    const float* wbhh_b = (const float*)d_in[22];
    const float* ff1_W  = (const float*)d_in[23];
    const float* ff1_b  = (const float*)d_in[24];
    const float* ff2_W  = (const float*)d_in[25];
    const float* ff2_b  = (const float*)d_in[26];
    const float* trans  = (const float*)d_in[27];
    const float* start_trans = (const float*)d_in[28];
    const float* end_trans   = (const float*)d_in[29];
    float* out = (float*)d_out;

    __half *pxh, *pxl, *pwihh, *pwihl, *pench, *pencl, *ph1h, *ph1l;
    __half *pff1h, *pff1l, *pff2h, *pff2l;
    float *pwx, *plog;
    cudaGetSymbolAddress((void**)&pxh,   g_x_h);
    cudaGetSymbolAddress((void**)&pxl,   g_x_l);
    cudaGetSymbolAddress((void**)&pwihh, g_wih_h);
    cudaGetSymbolAddress((void**)&pwihl, g_wih_l);
    cudaGetSymbolAddress((void**)&pwx,   g_wxproj);
    cudaGetSymbolAddress((void**)&pench, g_enc_h);
    cudaGetSymbolAddress((void**)&pencl, g_enc_l);
    cudaGetSymbolAddress((void**)&ph1h,  g_h1_h);
    cudaGetSymbolAddress((void**)&ph1l,  g_h1_l);
    cudaGetSymbolAddress((void**)&plog,  g_logits);
    cudaGetSymbolAddress((void**)&pff1h, g_ff1w_h);
    cudaGetSymbolAddress((void**)&pff1l, g_ff1w_l);
    cudaGetSymbolAddress((void**)&pff2h, g_ff2w_h);
    cudaGetSymbolAddress((void**)&pff2l, g_ff2w_l);

    const size_t wih_per = (size_t)4 * Hw_ * Kp_;
    const size_t wx_per = (size_t)NC_ * 4 * Hw_;

    const int ge_smem = 2 * G64_STAGE * 2;     // 60 KB (3 blocks/SM)
    const int ch_smem = 2 * CSH_STAGE * 2;     // 60 KB (3 blocks/SM)
    const int wp_smem = WP_SMEM_BYTES;         // ~123 KB
    cudaFuncSetAttribute(hmma_gemm, cudaFuncAttributeMaxDynamicSharedMemorySize, ge_smem);
    cudaFuncSetAttribute(char_step_kernel, cudaFuncAttributeMaxDynamicSharedMemorySize, ch_smem);
    cudaFuncSetAttribute(word_persistent, cudaFuncAttributeMaxDynamicSharedMemorySize, wp_smem);

    // 0) merged prep + vocab proj
    prep_kernel<<<2048, 256>>>(out, out_size, wWih_f, wWih_b, cWhh_f, cWhh_b, ff1_W, ff2_W);
    char_vocab_proj<<<2 * VC_, 256>>>(char_emb, cWih_f, cbih_f, cbhh_f, cWih_b, cbih_b, cbhh_b);

    // 1) char BiLSTM (M=64 tiles, 3 blocks/SM)
    for (int t = 0; t < W_; t++)
        char_step_kernel<<<dim3(4, NC_ / 64, 2), 256, ch_smem>>>(char_inputs, t);

    // 2) build padded word input (fp16 planes)
    build_x_kernel<<<(NC_ * Kp_ + 255) / 256, 256>>>(word_inputs, cap_inputs, word_emb, cap_emb);

    // 3) word input projections (M=64 tiles)
    hmma_gemm<<<dim3(4 * Hw_ / 128, NC_ / 64), 256, ge_smem>>>(
        pxh, pxl, pwihh, pwihl, wbih_f, wbhh_f, pwx, nullptr, nullptr, NC_, 4 * Hw_, Kp_, 0);
    hmma_gemm<<<dim3(4 * Hw_ / 128, NC_ / 64), 256, ge_smem>>>(
        pxh, pxl, pwihh + wih_per, pwihl + wih_per, wbih_b, wbhh_b,
        pwx + wx_per, nullptr, nullptr, NC_, 4 * Hw_, Kp_, 0);

    // 4) persistent word BiLSTM (R13 config: 128 blocks, j-tile 8)
    word_persistent<<<128, 256, wp_smem>>>(wWhh_f, wWhh_b);

    // 5) feed-forward head
    hmma_gemm<<<dim3(Hw_ / 128, NC_ / 64), 256, ge_smem>>>(
        pench, pencl, pff1h, pff1l, ff1_b, nullptr, nullptr, ph1h, ph1l, NC_, Hw_, 2 * Hw_, 1);
    hmma_gemm<<<dim3(1, NC_ / 64), 256, ge_smem>>>(
        ph1h, ph1l, pff2h, pff2l, ff2_b, nullptr, plog, nullptr, nullptr, NC_, T_, Hw_, 0);

    // 6) CRF forward + Viterbi, then loss
    crf_fwd_kernel<<<2 * B_, T_>>>(trans, start_trans, end_trans, out, out_size);
    crf_loss_kernel<<<1, B_>>>(tag_inputs, trans, start_trans, end_trans, out, out_size);
}

// round 16
// speedup vs baseline: 1.1632x; 1.0627x over previous
#include <cuda_runtime.h>
#include <cuda_fp16.h>
#include <stdint.h>
#include <math.h>

// ---------------- problem constants ----------------
#define S_   256
#define B_   64
#define W_   16
#define Ec_  64
#define Hc_  128
#define E_   300
#define Hw_  512
#define T_   32
#define D_   557
#define Kp_  576
#define NC_  (B_ * S_)
#define VC_  128

// ---------------- scratch: fp16 hi/lo planes for all MMA operands ----------------
__device__ __align__(16) __half g_ch_h[2][2][NC_ * Hc_];
__device__ __align__(16) __half g_ch_l[2][2][NC_ * Hc_];
__device__ float g_char_c[2][NC_ * Hc_];
__device__ float g_cproj[2][VC_ * 4 * Hc_];
__device__ __align__(16) __half g_cwhh_h[2][4 * Hc_ * Hc_];
__device__ __align__(16) __half g_cwhh_l[2][4 * Hc_ * Hc_];
__device__ __align__(16) __half g_x_h[(size_t)NC_ * Kp_];
__device__ __align__(16) __half g_x_l[(size_t)NC_ * Kp_];
__device__ __align__(16) __half g_wih_h[2][4 * Hw_ * Kp_];
__device__ __align__(16) __half g_wih_l[2][4 * Hw_ * Kp_];
__device__ float g_wxproj[2][(size_t)NC_ * 4 * Hw_];
__device__ __align__(16) __half g_wh_h[2][2][B_ * Hw_];
__device__ __align__(16) __half g_wh_l[2][2][B_ * Hw_];
__device__ float g_word_c[2][B_ * Hw_];
__device__ __align__(16) __half g_enc_h[(size_t)NC_ * 2 * Hw_];
__device__ __align__(16) __half g_enc_l[(size_t)NC_ * 2 * Hw_];
__device__ __align__(16) __half g_h1_h[(size_t)NC_ * Hw_];
__device__ __align__(16) __half g_h1_l[(size_t)NC_ * Hw_];
__device__ __align__(16) __half g_ff1w_h[Hw_ * 2 * Hw_];
__device__ __align__(16) __half g_ff1w_l[Hw_ * 2 * Hw_];
__device__ __align__(16) __half g_ff2w_h[T_ * Hw_];
__device__ __align__(16) __half g_ff2w_l[T_ * Hw_];
__device__ float g_logits[NC_ * T_];
__device__ float g_logZ[B_];
__device__ volatile int g_bar_count[2];
__device__ volatile int g_bar_gen[2];

__device__ __forceinline__ float sigf(float x) { return 1.0f / (1.0f + expf(-x)); }

__device__ __forceinline__ void split2h(float v, __half& h, __half& l) {
    __half hh = __float2half_rn(v);
    h = hh;
    l = __float2half_rn(v - __half2float(hh));
}

// fp16 m16n8k16 mma, fp32 accumulate
__device__ __forceinline__ void mma16(float* c, const unsigned* a, const unsigned* b) {
    asm volatile(
        "mma.sync.aligned.m16n8k16.row.col.f32.f16.f16.f32 "
        "{%0,%1,%2,%3}, {%4,%5,%6,%7}, {%8,%9}, {%0,%1,%2,%3};"
        : "+f"(c[0]), "+f"(c[1]), "+f"(c[2]), "+f"(c[3])
        : "r"(a[0]), "r"(a[1]), "r"(a[2]), "r"(a[3]), "r"(b[0]), "r"(b[1]));
}
__device__ __forceinline__ void mma3h(float* c, const unsigned* ah, const unsigned* al,
                                      const unsigned* bh, const unsigned* bl) {
    mma16(c, al, bh);
    mma16(c, ah, bl);
    mma16(c, ah, bh);
}

// warp-collective ldmatrix
__device__ __forceinline__ void ldm_x4(unsigned* r, uint32_t saddr) {
    asm volatile("ldmatrix.sync.aligned.m8n8.x4.shared.b16 {%0,%1,%2,%3}, [%4];"
        : "=r"(r[0]), "=r"(r[1]), "=r"(r[2]), "=r"(r[3]) : "r"(saddr));
}

// cp.async helpers
__device__ __forceinline__ void cpa16(uint32_t saddr, const void* gptr) {
    asm volatile("cp.async.ca.shared.global [%0], [%1], 16;" :: "r"(saddr), "l"(gptr));
}
__device__ __forceinline__ void cpa_commit() { asm volatile("cp.async.commit_group;"); }
__device__ __forceinline__ void cpa_wait0() { asm volatile("cp.async.wait_group 0;"); }

// ---------------- merged prep kernel ----------------
__global__ void __launch_bounds__(256)
prep_kernel(float* __restrict__ out, int out_size,
            const float* __restrict__ wWf, const float* __restrict__ wWb,
            const float* __restrict__ cWhhF, const float* __restrict__ cWhhB,
            const float* __restrict__ ff1W, const float* __restrict__ ff2W)
{
    const int stride = gridDim.x * blockDim.x;
    const int i0 = blockIdx.x * blockDim.x + threadIdx.x;
    const __half hz = __float2half(0.0f);
    for (int i = i0; i < out_size; i += stride) out[i] = 0.0f;
    for (size_t i = i0; i < (size_t)2 * 2 * NC_ * Hc_; i += stride) {
        (&g_ch_h[0][0][0])[i] = hz;
        (&g_ch_l[0][0][0])[i] = hz;
    }
    for (int i = i0; i < 2 * NC_ * Hc_; i += stride)
        (&g_char_c[0][0])[i] = 0.0f;
    for (int i = i0; i < 2 * 2 * B_ * Hw_; i += stride) {
        (&g_wh_h[0][0][0])[i] = hz;
        (&g_wh_l[0][0][0])[i] = hz;
    }
    for (int i = i0; i < 2 * B_ * Hw_; i += stride)
        (&g_word_c[0][0])[i] = 0.0f;
    const int per = 4 * Hw_ * Kp_;
    for (int idx = i0; idx < 2 * per; idx += stride) {
        int dir = idx / per;
        int r = idx - dir * per;
        int n = r / Kp_, k = r - n * Kp_;
        const float* Wsrc = dir ? wWb : wWf;
        float v = (k < D_) ? Wsrc[(size_t)n * D_ + k] : 0.0f;
        split2h(v, g_wih_h[dir][r], g_wih_l[dir][r]);
    }
    const int cn = 4 * Hc_ * Hc_;
    for (int i = i0; i < cn; i += stride) {
        split2h(cWhhF[i], g_cwhh_h[0][i], g_cwhh_l[0][i]);
        split2h(cWhhB[i], g_cwhh_h[1][i], g_cwhh_l[1][i]);
    }
    for (int i = i0; i < Hw_ * 2 * Hw_; i += stride)
        split2h(ff1W[i], g_ff1w_h[i], g_ff1w_l[i]);
    for (int i = i0; i < T_ * Hw_; i += stride)
        split2h(ff2W[i], g_ff2w_h[i], g_ff2w_l[i]);
}

__global__ void __launch_bounds__(256)
char_vocab_proj(const float* __restrict__ emb,
                const float* __restrict__ WihF, const float* __restrict__ bihF,
                const float* __restrict__ bhhF,
                const float* __restrict__ WihB, const float* __restrict__ bihB,
                const float* __restrict__ bhhB)
{
    int dir = blockIdx.x >> 7;
    int cid = blockIdx.x & 127;
    const float* Wih = dir ? WihB : WihF;
    const float* bih = dir ? bihB : bihF;
    const float* bhh = dir ? bhhB : bhhF;
    __shared__ float e[Ec_];
    if (threadIdx.x < Ec_) e[threadIdx.x] = emb[cid * Ec_ + threadIdx.x];
    __syncthreads();
    for (int n = threadIdx.x; n < 4 * Hc_; n += 256) {
        float s = bih[n] + bhh[n];
        const float* wr = &Wih[(size_t)n * Ec_];
#pragma unroll 8
        for (int k = 0; k < Ec_; k++) s += e[k] * wr[k];
        g_cproj[dir][cid * 4 * Hc_ + n] = s;
    }
}

__global__ void __launch_bounds__(256)
build_x_kernel(const int* __restrict__ wid, const int* __restrict__ cap,
               const float* __restrict__ wemb, const float* __restrict__ cemb)
{
    int idx = blockIdx.x * blockDim.x + threadIdx.x;
    if (idx >= NC_ * Kp_) return;
    int d = idx % Kp_;
    int sb = idx / Kp_;
    int s = sb / B_, b = sb % B_;
    float v = 0.0f;
    if (d < E_) {
        v = wemb[(size_t)wid[s * B_ + b] * E_ + d];
    } else if (d < E_ + 2 * Hc_) {
        int j = d - E_;
        int n = b * S_ + s;
        size_t off = (j < Hc_) ? ((size_t)n * Hc_ + j) : ((size_t)n * Hc_ + (j - Hc_));
        int dd = (j < Hc_) ? 0 : 1;
        v = __half2float(g_ch_h[dd][0][off]) + __half2float(g_ch_l[dd][0][off]);
    } else if (d == E_ + 2 * Hc_) {
        v = cemb[cap[s * B_ + b]];
    }
    split2h(v, g_x_h[idx], g_x_l[idx]);
}

// ---------------- 3xFP16 GEMM (R13 config: tile M=128, N=128, K=32/stage) --------
#define GEH_PITCH 40
#define GEH_PLANE (128 * GEH_PITCH)   // 5120 halves
#define GEH_STAGE (4 * GEH_PLANE)     // 20480 halves = 40 KB
__global__ void __launch_bounds__(256, 2)
hmma_gemm(const __half* __restrict__ AH, const __half* __restrict__ AL,
          const __half* __restrict__ WH, const __half* __restrict__ WL,
          const float* __restrict__ b1, const float* __restrict__ b2,
          float* __restrict__ C, __half* __restrict__ Ch, __half* __restrict__ Cl,
          int M, int N, int K, int act)
{
    extern __shared__ __align__(16) __half smh[];
    const int tid = threadIdx.x;
    const int w = tid >> 5, l = tid & 31;
    const int wm = w & 1, wn = w >> 1;
    const int g = l >> 2, tg = l & 3;
    const int sub = l >> 3, ri = l & 7;
    const int a_ro = ((sub & 1) << 3) + ri;
    const int a_ko = (sub >> 1) << 3;
    const int b_ro = ((sub >> 1) << 3) + ri;
    const int b_ko = (sub & 1) << 3;
    const int m0 = blockIdx.y * 128, n0 = blockIdx.x * 128;
    const uint32_t sbase = (uint32_t)__cvta_generic_to_shared(smh);

    float acc[4][4][4] = {};
    const int KT = K >> 5;

    auto issue = [&](int kt, int stage) {
        uint32_t sa = sbase + (uint32_t)(stage * GEH_STAGE) * 2;
#pragma unroll
        for (int q = 0; q < 8; q++) {
            int i = tid + q * 256;
            int p = i >> 9;
            int r = (i & 511) >> 2;
            int ch = i & 3;
            const __half* gp = (p == 0) ? AH : (p == 1) ? AL : (p == 2) ? WH : WL;
            int row = (p < 2) ? (m0 + r) : (n0 + r);
            if (p >= 2 && row >= N) row = N - 1;   // clamp; never stored
            size_t go = (size_t)row * K + kt * 32 + ch * 8;
            cpa16(sa + (uint32_t)(p * GEH_PLANE + r * GEH_PITCH + ch * 8) * 2, gp + go);
        }
        cpa_commit();
    };

    issue(0, 0);
    for (int kt = 0; kt < KT; kt++) {
        cpa_wait0();
        __syncthreads();
        if (kt + 1 < KT) issue(kt + 1, (kt + 1) & 1);
        uint32_t stA  = sbase + (uint32_t)((kt & 1) * GEH_STAGE) * 2;
        uint32_t stAl = stA + (uint32_t)GEH_PLANE * 2;
        uint32_t stW  = stA + (uint32_t)(2 * GEH_PLANE) * 2;
        uint32_t stWl = stA + (uint32_t)(3 * GEH_PLANE) * 2;
#pragma unroll
        for (int ks = 0; ks < 2; ks++) {
            unsigned ah[4][4], al[4][4], bh2[2][4], bl2[2][4];
#pragma unroll
            for (int mi = 0; mi < 4; mi++) {
                uint32_t off = (uint32_t)((wm * 64 + mi * 16 + a_ro) * GEH_PITCH
                                          + ks * 16 + a_ko) * 2;
                ldm_x4(ah[mi], stA + off);
                ldm_x4(al[mi], stAl + off);
            }
#pragma unroll
            for (int nq = 0; nq < 2; nq++) {
                uint32_t off = (uint32_t)((wn * 32 + nq * 16 + b_ro) * GEH_PITCH
                                          + ks * 16 + b_ko) * 2;
                ldm_x4(bh2[nq], stW + off);
                ldm_x4(bl2[nq], stWl + off);
            }
#pragma unroll
            for (int mi = 0; mi < 4; mi++)
#pragma unroll
                for (int nq = 0; nq < 2; nq++) {
                    mma3h(acc[mi][2 * nq],     ah[mi], al[mi], bh2[nq],     bl2[nq]);
                    mma3h(acc[mi][2 * nq + 1], ah[mi], al[mi], bh2[nq] + 2, bl2[nq] + 2);
                }
        }
    }
#pragma unroll
    for (int mi = 0; mi < 4; mi++) {
#pragma unroll
        for (int ni = 0; ni < 4; ni++) {
            int m = m0 + wm * 64 + mi * 16 + g;
            int n = n0 + wn * 32 + ni * 8 + 2 * tg;
#pragma unroll
            for (int q = 0; q < 4; q++) {
                int mm = m + (q >> 1) * 8;
                int nn = n + (q & 1);
                if (nn >= N) continue;
                float v = acc[mi][ni][q];
                if (b1) v += b1[nn];
                if (b2) v += b2[nn];
                if (act == 1) v = tanhf(v);
                size_t off = (size_t)mm * N + nn;
                if (Ch) split2h(v, Ch[off], Cl[off]);
                else C[off] = v;
            }
        }
    }
}

// ---------------- fused char LSTM step: M=64, N=128, K=128 (fp16, 3 blocks/SM) ---
#define CSH_APLANE (64 * 40)
#define CSH_WPLANE (128 * 40)
#define CSH_STAGE  (2 * CSH_APLANE + 2 * CSH_WPLANE)   // 15360 halves = 30 KB
__global__ void __launch_bounds__(256, 3)
char_step_kernel(const int* __restrict__ cin, int t)
{
    const int dir = blockIdx.z;
    const int t_eff = dir ? (W_ - 1 - t) : t;
    const __half* hpH = g_ch_h[dir][t & 1];
    const __half* hpL = g_ch_l[dir][t & 1];
    __half* hnH = g_ch_h[dir][(t + 1) & 1];
    __half* hnL = g_ch_l[dir][(t + 1) & 1];
    float* cst = g_char_c[dir];
    const __half* WhS = g_cwhh_h[dir];
    const __half* WlS = g_cwhh_l[dir];
    const float* proj = g_cproj[dir];

    extern __shared__ __align__(16) __half smh[];
    float (*zb)[132] = (float(*)[132])smh;
    const uint32_t sbase = (uint32_t)__cvta_generic_to_shared(smh);

    const int tid = threadIdx.x;
    const int w = tid >> 5, l = tid & 31;
    const int wm = w & 1, wn = w >> 1;
    const int g = l >> 2, tg = l & 3;
    const int sub = l >> 3, ri = l & 7;
    const int a_ro = ((sub & 1) << 3) + ri;
    const int a_ko = (sub >> 1) << 3;
    const int b_ro = ((sub >> 1) << 3) + ri;
    const int b_ko = (sub & 1) << 3;
    const int j0 = blockIdx.x * 32;
    const int m0 = blockIdx.y * 64;

    float acc[2][4][4] = {};

    auto issue = [&](int kt, int stage) {
        uint32_t sa = sbase + (uint32_t)(stage * CSH_STAGE) * 2;
#pragma unroll
        for (int q = 0; q < 6; q++) {
            int i = tid + q * 256;
            if (i < 512) {
                int p = i >> 8;
                int r = (i & 255) >> 2;
                int ch = i & 3;
                const __half* gp = p ? hpL : hpH;
                size_t go = (size_t)(m0 + r) * Hc_ + kt * 32 + ch * 8;
                cpa16(sa + (uint32_t)(p * CSH_APLANE + r * 40 + ch * 8) * 2, gp + go);
            } else {
                int j = i - 512;
                int p = j >> 9;
                int r = (j & 511) >> 2;
                int ch = j & 3;
                const __half* gp = p ? WlS : WhS;
                int wr = (r >> 5) * Hc_ + j0 + (r & 31);
                size_t go = (size_t)wr * Hc_ + kt * 32 + ch * 8;
                cpa16(sa + (uint32_t)(2 * CSH_APLANE + p * CSH_WPLANE + r * 40 + ch * 8) * 2,
                      gp + go);
            }
        }
        cpa_commit();
    };

    issue(0, 0);
#pragma unroll 1
    for (int kt = 0; kt < 4; kt++) {
        cpa_wait0();
        __syncthreads();
        if (kt + 1 < 4) issue(kt + 1, (kt + 1) & 1);
        uint32_t stA  = sbase + (uint32_t)((kt & 1) * CSH_STAGE) * 2;
        uint32_t stAl = stA + (uint32_t)CSH_APLANE * 2;
        uint32_t stW  = stA + (uint32_t)(2 * CSH_APLANE) * 2;
        uint32_t stWl = stW + (uint32_t)CSH_WPLANE * 2;
#pragma unroll
        for (int ks = 0; ks < 2; ks++) {
            unsigned ah[2][4], al[2][4], bh2[2][4], bl2[2][4];
#pragma unroll
            for (int mi = 0; mi < 2; mi++) {
                uint32_t off = (uint32_t)((wm * 32 + mi * 16 + a_ro) * 40
                                          + ks * 16 + a_ko) * 2;
                ldm_x4(ah[mi], stA + off);
                ldm_x4(al[mi], stAl + off);
            }
#pragma unroll
            for (int nq = 0; nq < 2; nq++) {
                uint32_t off = (uint32_t)((wn * 32 + nq * 16 + b_ro) * 40
                                          + ks * 16 + b_ko) * 2;
                ldm_x4(bh2[nq], stW + off);
                ldm_x4(bl2[nq], stWl + off);
            }
#pragma unroll
            for (int mi = 0; mi < 2; mi++)
#pragma unroll
                for (int nq = 0; nq < 2; nq++) {
                    mma3h(acc[mi][2 * nq],     ah[mi], al[mi], bh2[nq],     bl2[nq]);
                    mma3h(acc[mi][2 * nq + 1], ah[mi], al[mi], bh2[nq] + 2, bl2[nq] + 2);
                }
        }
    }
    __syncthreads();
#pragma unroll
    for (int mi = 0; mi < 2; mi++) {
#pragma unroll
        for (int ni = 0; ni < 4; ni++) {
            int row = wm * 32 + mi * 16 + g;
            int col = wn * 32 + ni * 8 + 2 * tg;
            zb[row][col]         = acc[mi][ni][0];
            zb[row][col + 1]     = acc[mi][ni][1];
            zb[row + 8][col]     = acc[mi][ni][2];
            zb[row + 8][col + 1] = acc[mi][ni][3];
        }
    }
    __syncthreads();
    for (int idx = tid; idx < 64 * 32; idx += 256) {
        int ml = idx >> 5, jj = idx & 31;
        int j = j0 + jj;
        int m = m0 + ml;
        int cid = cin[m * W_ + t_eff];
        const float* pr = &proj[(size_t)cid * 4 * Hc_];
        float zi = zb[ml][jj]      + pr[j];
        float zf = zb[ml][32 + jj] + pr[Hc_ + j];
        float zg = zb[ml][64 + jj] + pr[2 * Hc_ + j];
        float zo = zb[ml][96 + jj] + pr[3 * Hc_ + j];
        size_t off = (size_t)m * Hc_ + j;
        float c = cst[off];
        c = sigf(zf) * c + sigf(zi) * tanhf(zg);
        cst[off] = c;
        float hv = sigf(zo) * tanhf(c);
        split2h(hv, hnH[off], hnL[off]);
    }
}

// ---------------- persistent word BiLSTM: j-tile 8, 128 blocks, K-chunk 128 ------
#define WPH_WPITCH 520
#define WPH_WPLANE (32 * WPH_WPITCH)   // 16640 halves
#define WPH_APITCH 136
#define WPH_APLANE (64 * WPH_APITCH)   // 8704 halves
#define WPH_ASTAGE (2 * WPH_APLANE)    // 17408 halves (hi+lo)
#define WPH_HALVES (2 * WPH_WPLANE + 2 * WPH_ASTAGE)   // 68096
#define WP_ZB  (64 * 36)
#define WP_XS  (64 * 40)
#define WP_SMEM_BYTES (WPH_HALVES * 2 + (WP_ZB + WP_XS) * 4)
__device__ __forceinline__ void grid_bar_dir(int dir) {
    __syncthreads();
    if (threadIdx.x == 0) {
        __threadfence();
        int gen = g_bar_gen[dir];
        if (atomicAdd((int*)&g_bar_count[dir], 1) == 63) {
            g_bar_count[dir] = 0;
            __threadfence();
            g_bar_gen[dir] = gen + 1;
        } else {
            while (g_bar_gen[dir] == gen) __nanosleep(20);
            __threadfence();
        }
    }
    __syncthreads();
}

__global__ void __launch_bounds__(256)
word_persistent(const float* __restrict__ WhhF, const float* __restrict__ WhhB)
{
    extern __shared__ __align__(16) __half smh[];
    __half* Wh = smh;
    __half* Wl = smh + WPH_WPLANE;
    float* zbf = (float*)(smh + WPH_HALVES);
    float (*zb)[36] = (float(*)[36])zbf;
    float* xs = zbf + WP_ZB;
    const uint32_t sbase = (uint32_t)__cvta_generic_to_shared(smh);
    const uint32_t sWl = sbase + (uint32_t)WPH_WPLANE * 2;
    const uint32_t ab_sa = sbase + (uint32_t)(2 * WPH_WPLANE) * 2;
    const uint32_t xs_sa = sbase + (uint32_t)WPH_HALVES * 2 + (uint32_t)WP_ZB * 4;

    const int dir = blockIdx.x >> 6;
    const int jb = blockIdx.x & 63;
    const int j0 = jb * 8;
    const int tid = threadIdx.x;
    const int w = tid >> 5, l = tid & 31;
    const int wm = w & 3, wn = w >> 2;
    const int g = l >> 2, tg = l & 3;
    const int sub = l >> 3, ri = l & 7;
    const int a_ro = ((sub & 1) << 3) + ri;
    const int a_ko = (sub >> 1) << 3;
    const int b_ro = ((sub >> 1) << 3) + ri;
    const int b_ko = (sub & 1) << 3;

    const float* Whh = dir ? WhhB : WhhF;
    for (int i = tid; i < 32 * 512; i += 256) {
        int rr = i >> 9, k = i & 511;
        int wr = (rr >> 3) * Hw_ + j0 + (rr & 7);
        split2h(Whh[(size_t)wr * Hw_ + k], Wh[rr * WPH_WPITCH + k], Wl[rr * WPH_WPITCH + k]);
    }
    __syncthreads();

    const float* xbase = g_wxproj[dir];
    float* cst = g_word_c[dir];

    for (int t = 0; t < S_; t++) {
        const int s = dir ? (S_ - 1 - t) : t;
        const __half* hpH = g_wh_h[dir][t & 1];
        const __half* hpL = g_wh_l[dir][t & 1];
        __half* hnH = g_wh_h[dir][(t + 1) & 1];
        __half* hnL = g_wh_l[dir][(t + 1) & 1];

        // K-chunk 128: 4 ko iterations, A-stage 64 x 128 halves per plane
        auto issueA = [&](int ko, int stage) {
            uint32_t sa = ab_sa + (uint32_t)(stage * WPH_ASTAGE) * 2;
#pragma unroll
            for (int q = 0; q < 8; q++) {
                int i = tid + q * 256;        // 0..2047
                int p = i >> 10;
                int r = (i & 1023) >> 4;
                int ch = i & 15;
                const __half* gp = p ? hpL : hpH;
                size_t go = (size_t)r * Hw_ + ko * 128 + ch * 8;
                cpa16(sa + (uint32_t)(p * WPH_APLANE + r * WPH_APITCH + ch * 8) * 2, gp + go);
            }
        };

        issueA(0, 0);
#pragma unroll
        for (int q = 0; q < 2; q++) {
            int e = tid * 2 + q;
            int b = e >> 3, subb = e & 7;
            int gate = subb >> 1, half = subb & 1;
            const float* gp = xbase + ((size_t)s * B_ + b) * 4 * Hw_ + gate * Hw_ + j0 + half * 4;
            cpa16(xs_sa + (uint32_t)(b * 40 + gate * 8 + half * 4) * 4, gp);
        }
        cpa_commit();

        float acc[2][4] = {};
#pragma unroll 1
        for (int ko = 0; ko < 4; ko++) {
            cpa_wait0();
            __syncthreads();
            if (ko + 1 < 4) { issueA(ko + 1, (ko + 1) & 1); cpa_commit(); }
            uint32_t stAh = ab_sa + (uint32_t)((ko & 1) * WPH_ASTAGE) * 2;
            uint32_t stAl = stAh + (uint32_t)WPH_APLANE * 2;
#pragma unroll
            for (int kc = 0; kc < 8; kc++) {
                unsigned ah[4], al[4], bh2[4], bl2[4];
                uint32_t aoff = (uint32_t)((wm * 16 + a_ro) * WPH_APITCH
                                           + kc * 16 + a_ko) * 2;
                ldm_x4(ah, stAh + aoff);
                ldm_x4(al, stAl + aoff);
                uint32_t boff = (uint32_t)((wn * 16 + b_ro) * WPH_WPITCH
                                           + ko * 128 + kc * 16 + b_ko) * 2;
                ldm_x4(bh2, sbase + boff);
                ldm_x4(bl2, sWl + boff);
                mma3h(acc[0], ah, al, bh2,     bl2);
                mma3h(acc[1], ah, al, bh2 + 2, bl2 + 2);
            }
        }
#pragma unroll
        for (int ni = 0; ni < 2; ni++) {
            int row = wm * 16 + g;
            int col = wn * 16 + ni * 8 + 2 * tg;
            zb[row][col]         = acc[ni][0];
            zb[row][col + 1]     = acc[ni][1];
            zb[row + 8][col]     = acc[ni][2];
            zb[row + 8][col + 1] = acc[ni][3];
        }
        __syncthreads();
        for (int idx = tid; idx < 512; idx += 256) {
            int b = idx >> 3, jj = idx & 7;
            int j = j0 + jj;
            const float* xr = xs + b * 40;
            float zi = zb[b][jj]      + xr[jj];
            float zf = zb[b][8 + jj]  + xr[8 + jj];
            float zg = zb[b][16 + jj] + xr[16 + jj];
            float zo = zb[b][24 + jj] + xr[24 + jj];
            size_t off = (size_t)b * Hw_ + j;
            float c = cst[off];
            c = sigf(zf) * c + sigf(zi) * tanhf(zg);
            cst[off] = c;
            float hv = sigf(zo) * tanhf(c);
            __half hh, hl;
            split2h(hv, hh, hl);
            hnH[off] = hh; hnL[off] = hl;
            size_t eoff = ((size_t)s * B_ + b) * (2 * Hw_) + dir * Hw_ + j;
            g_enc_h[eoff] = hh; g_enc_l[eoff] = hl;
        }
        grid_bar_dir(dir);
    }
}

// ---------------- merged CRF forward + Viterbi ----------------
__global__ void __launch_bounds__(32)
crf_fwd_kernel(const float* __restrict__ trans, const float* __restrict__ start,
               const float* __restrict__ endv, float* __restrict__ out, int out_size)
{
    __shared__ float tr[T_][T_];
    __shared__ float vec[T_];
    __shared__ unsigned char bp[S_ - 1][T_];
    const int to = threadIdx.x;
    for (int i = to; i < T_ * T_; i += T_) tr[i / T_][i % T_] = trans[i];

    if (blockIdx.x < B_) {
        const int b = blockIdx.x;
        vec[to] = start[to] + g_logits[(size_t)(0 * B_ + b) * T_ + to];
        __syncthreads();
        for (int s = 1; s < S_; s++) {
            float m = -1e30f;
#pragma unroll
            for (int f = 0; f < T_; f++) m = fmaxf(m, vec[f] + tr[f][to]);
            float sum = 0.0f;
#pragma unroll
            for (int f = 0; f < T_; f++) sum += expf(vec[f] + tr[f][to] - m);
            float a = m + logf(sum) + g_logits[((size_t)s * B_ + b) * T_ + to];
            __syncthreads();
            vec[to] = a;
            __syncthreads();
        }
        float v = vec[to] + endv[to];
        float m = v;
#pragma unroll
        for (int o = 16; o > 0; o >>= 1) m = fmaxf(m, __shfl_xor_sync(0xffffffffu, m, o));
        float e = expf(v - m);
#pragma unroll
        for (int o = 16; o > 0; o >>= 1) e += __shfl_xor_sync(0xffffffffu, e, o);
        if (to == 0) g_logZ[b] = m + logf(e);
    } else {
        const int b = blockIdx.x - B_;
        vec[to] = start[to] + g_logits[(size_t)b * T_ + to];
        __syncthreads();
        for (int s = 1; s < S_; s++) {
            float best = -1e30f;
            int arg = 0;
#pragma unroll
            for (int f = 0; f < T_; f++) {
                float sc = vec[f] + tr[f][to];
                if (sc > best) { best = sc; arg = f; }
            }
            bp[s - 1][to] = (unsigned char)arg;
            float nv = best + g_logits[((size_t)s * B_ + b) * T_ + to];
            __syncthreads();
            vec[to] = nv;
            __syncthreads();
        }
        if (to == 0) {
            float best = -1e30f;
            int last = 0;
            for (int f = 0; f < T_; f++) {
                float sc = vec[f] + endv[f];
                if (sc > best) { best = sc; last = f; }
            }
            int tag = last;
            int base = 1 + b * S_;
            if (base + S_ - 1 < out_size) out[base + S_ - 1] = (float)tag;
            for (int s = S_ - 2; s >= 0; s--) {
                tag = bp[s][tag];
                if (base + s < out_size) out[base + s] = (float)tag;
            }
        }
    }
}

__global__ void __launch_bounds__(64)
crf_loss_kernel(const int* __restrict__ tags, const float* __restrict__ trans,
                const float* __restrict__ start, const float* __restrict__ endv,
                float* __restrict__ out, int out_size)
{
    __shared__ float red[B_];
    const int b = threadIdx.x;
    int prev = tags[0 * B_ + b];
    float score = start[prev];
    for (int s = 0; s < S_; s++) {
        int tg = tags[s * B_ + b];
        score += g_logits[((size_t)s * B_ + b) * T_ + tg];
        if (s > 0) score += trans[prev * T_ + tg];
        prev = tg;
    }
    score += endv[prev];
    red[b] = g_logZ[b] - score;
    __syncthreads();
    if (b == 0) {
        float t = 0.0f;
        for (int i = 0; i < B_; i++) t += red[i];
        if (out_size > 0) out[0] = t;
    }
}

// ---------------- host-side orchestration ----------------
extern "C" void kernel_launch(void* const* d_in, const int* in_sizes, int n_in,
                              void* d_out, int out_size) {
    (void)in_sizes; (void)n_in;
    const int*   word_inputs = (const int*)d_in[0];
    const int*   char_inputs = (const int*)d_in[1];
    const int*   cap_inputs  = (const int*)d_in[2];
    const int*   tag_inputs  = (const int*)d_in[3];
    const float* word_emb    = (const float*)d_in[4];
    const float* cap_emb     = (const float*)d_in[5];
    const float* char_emb    = (const float*)d_in[6];
    const float* cWih_f = (const float*)d_in[7];
    const float* cWhh_f = (const float*)d_in[8];
    const float* cbih_f = (const float*)d_in[9];
    const float* cbhh_f = (const float*)d_in[10];
    const float* cWih_b = (const float*)d_in[11];
    const float* cWhh_b = (const float*)d_in[12];
    const float* cbih_b = (const float*)d_in[13];
    const float* cbhh_b = (const float*)d_in[14];
    const float* wWih_f = (const float*)d_in[15];
    const float* wWhh_f = (const float*)d_in[16];
    const float* wbih_f = (const float*)d_in[17];
    const float* wbhh_f = (const float*)d_in[18];
    const float* wWih_b = (const float*)d_in[19];
    const float* wWhh_b = (const float*)d_in[20];
    const float* wbih_b = (const float*)d_in[21];
    const float* wbhh_b = (const float*)d_in[22];
    const float* ff1_W  = (const float*)d_in[23];
    const float* ff1_b  = (const float*)d_in[24];
    const float* ff2_W  = (const float*)d_in[25];
    const float* ff2_b  = (const float*)d_in[26];
    const float* trans  = (const float*)d_in[27];
    const float* start_trans = (const float*)d_in[28];
    const float* end_trans   = (const float*)d_in[29];
    float* out = (float*)d_out;

    __half *pxh, *pxl, *pwihh, *pwihl, *pench, *pencl, *ph1h, *ph1l;
    __half *pff1h, *pff1l, *pff2h, *pff2l;
    float *pwx, *plog;
    cudaGetSymbolAddress((void**)&pxh,   g_x_h);
    cudaGetSymbolAddress((void**)&pxl,   g_x_l);
    cudaGetSymbolAddress((void**)&pwihh, g_wih_h);
    cudaGetSymbolAddress((void**)&pwihl, g_wih_l);
    cudaGetSymbolAddress((void**)&pwx,   g_wxproj);
    cudaGetSymbolAddress((void**)&pench, g_enc_h);
    cudaGetSymbolAddress((void**)&pencl, g_enc_l);
    cudaGetSymbolAddress((void**)&ph1h,  g_h1_h);
    cudaGetSymbolAddress((void**)&ph1l,  g_h1_l);
    cudaGetSymbolAddress((void**)&plog,  g_logits);
    cudaGetSymbolAddress((void**)&pff1h, g_ff1w_h);
    cudaGetSymbolAddress((void**)&pff1l, g_ff1w_l);
    cudaGetSymbolAddress((void**)&pff2h, g_ff2w_h);
    cudaGetSymbolAddress((void**)&pff2l, g_ff2w_l);

    const size_t wih_per = (size_t)4 * Hw_ * Kp_;
    const size_t wx_per = (size_t)NC_ * 4 * Hw_;

    const int ge_smem = 2 * GEH_STAGE * 2;     // 80 KB (2 blocks/SM)
    const int ch_smem = 2 * CSH_STAGE * 2;     // 60 KB (3 blocks/SM)
    const int wp_smem = WP_SMEM_BYTES;         // ~156 KB (1 block/SM)
    cudaFuncSetAttribute(hmma_gemm, cudaFuncAttributeMaxDynamicSharedMemorySize, ge_smem);
    cudaFuncSetAttribute(char_step_kernel, cudaFuncAttributeMaxDynamicSharedMemorySize, ch_smem);
    cudaFuncSetAttribute(word_persistent, cudaFuncAttributeMaxDynamicSharedMemorySize, wp_smem);

    // 0) merged prep + vocab proj
    prep_kernel<<<2048, 256>>>(out, out_size, wWih_f, wWih_b, cWhh_f, cWhh_b, ff1_W, ff2_W);
    char_vocab_proj<<<2 * VC_, 256>>>(char_emb, cWih_f, cbih_f, cbhh_f, cWih_b, cbih_b, cbhh_b);

    // 1) char BiLSTM (M=64 tiles, 3 blocks/SM)
    for (int t = 0; t < W_; t++)
        char_step_kernel<<<dim3(4, NC_ / 64, 2), 256, ch_smem>>>(char_inputs, t);

    // 2) build padded word input (fp16 planes)
    build_x_kernel<<<(NC_ * Kp_ + 255) / 256, 256>>>(word_inputs, cap_inputs, word_emb, cap_emb);

    // 3) word input projections (M=128 tiles — R13 config)
    hmma_gemm<<<dim3(4 * Hw_ / 128, NC_ / 128), 256, ge_smem>>>(
        pxh, pxl, pwihh, pwihl, wbih_f, wbhh_f, pwx, nullptr, nullptr, NC_, 4 * Hw_, Kp_, 0);
    hmma_gemm<<<dim3(4 * Hw_ / 128, NC_ / 128), 256, ge_smem>>>(
        pxh, pxl, pwihh + wih_per, pwihl + wih_per, wbih_b, wbhh_b,
        pwx + wx_per, nullptr, nullptr, NC_, 4 * Hw_, Kp_, 0);

    // 4) persistent word BiLSTM (128 blocks, j-tile 8, K-chunk 128)
    word_persistent<<<128, 256, wp_smem>>>(wWhh_f, wWhh_b);

    // 5) feed-forward head
    hmma_gemm<<<dim3(Hw_ / 128, NC_ / 128), 256, ge_smem>>>(
        pench, pencl, pff1h, pff1l, ff1_b, nullptr, nullptr, ph1h, ph1l, NC_, Hw_, 2 * Hw_, 1);
    hmma_gemm<<<dim3(1, NC_ / 128), 256, ge_smem>>>(
        ph1h, ph1l, pff2h, pff2l, ff2_b, nullptr, plog, nullptr, nullptr, NC_, T_, Hw_, 0);

    // 6) CRF forward + Viterbi, then loss
    crf_fwd_kernel<<<2 * B_, T_>>>(trans, start_trans, end_trans, out, out_size);
    crf_loss_kernel<<<1, B_>>>(tag_inputs, trans, start_trans, end_trans, out, out_size);
}